// round 10
// baseline (speedup 1.0000x reference)
#include <cuda_runtime.h>
#include <cuda_bf16.h>
#include <math.h>
#include <stdint.h>

// Problem constants
#define Bc   2
#define Lc   2048
#define Dc   1024
#define Hc   16
#define HDc  64
#define Mtot (Bc*Lc)      // 4096
#define BHL  (Bc*Hc*Lc)   // 65536

// ---- scratch (device globals: allocation-free, graph-capturable) ----
__device__ float  g_q[(size_t)BHL*HDc];     // [B,H,L,HD] (q pre-scaled by 0.125)
__device__ float  g_k[(size_t)BHL*HDc];     // [B,H,L,HD]
__device__ float  g_vt[(size_t)BHL*HDc];    // [B,H,HD,L]  (V transposed)
__device__ float  g_ctx[(size_t)Mtot*Dc];   // [B,L,D]
__device__ float  g_x[(size_t)Mtot*Dc];     // pre-LN
__device__ float2 g_cs[BHL];                // (cos phi, sin phi) per (b,h,l)

// ---- helpers ----
__device__ __forceinline__ uint32_t pkbf2(float lo, float hi) {
    __nv_bfloat162 h = __float22bfloat162_rn(make_float2(lo, hi));
    return *(uint32_t*)&h;
}
// bf16 mma m16n8k16, fp32 accumulate
__device__ __forceinline__ void mma_bf16(float* c, const uint32_t* a,
                                         uint32_t b0, uint32_t b1)
{
    asm volatile(
        "mma.sync.aligned.m16n8k16.row.col.f32.bf16.bf16.f32 "
        "{%0,%1,%2,%3}, {%4,%5,%6,%7}, {%8,%9}, {%0,%1,%2,%3};"
        : "+f"(c[0]), "+f"(c[1]), "+f"(c[2]), "+f"(c[3])
        : "r"(a[0]), "r"(a[1]), "r"(a[2]), "r"(a[3]), "r"(b0), "r"(b1));
}
__device__ __forceinline__ uint32_t smem_u32(const void* p) {
    return (uint32_t)__cvta_generic_to_shared(p);
}
__device__ __forceinline__ void ldsm_x4(uint32_t* r, uint32_t addr) {
    asm volatile("ldmatrix.sync.aligned.m8n8.x4.shared.b16 {%0,%1,%2,%3}, [%4];"
                 : "=r"(r[0]), "=r"(r[1]), "=r"(r[2]), "=r"(r[3]) : "r"(addr));
}

// ============================================================
// bf16 tile GEMM with ldmatrix + double-buffered smem.
// out = A @ W^T + bias (+ residual for MODE 1)
// 128x128 tile, K-chunk 32, 256 thr = 8 warps (2m x 4n), warp tile 64x32.
// MODE 0, z==2 (V): epilogue writes TRANSPOSED [bh][d][l].
// ============================================================
template<int MODE>
__global__ __launch_bounds__(256)
void gemm_kernel(const float* __restrict__ Ain,
                 const float* __restrict__ W0, const float* __restrict__ bias0,
                 const float* __restrict__ W1, const float* __restrict__ bias1,
                 const float* __restrict__ W2, const float* __restrict__ bias2,
                 const float* __restrict__ residual)
{
    const float* A; const float* W; const float* bias; float* out;
    const int z = (MODE == 0) ? blockIdx.z : 0;
    if (MODE == 0) {
        A = Ain;
        W    = (z == 0) ? W0    : (z == 1) ? W1    : W2;
        bias = (z == 0) ? bias0 : (z == 1) ? bias1 : bias2;
        out  = (z == 0) ? g_q   : (z == 1) ? g_k   : g_vt;
    } else {
        A = g_ctx; W = W0; bias = bias0; out = g_x;
    }

    __shared__ uint32_t Au[2][128][20];
    __shared__ uint32_t Wu[2][128][20];

    const int tid  = threadIdx.x;
    const int lane = tid & 31;
    const int wid  = tid >> 5;
    const int g    = lane >> 2, tg = lane & 3;
    const int warpM = wid & 1, warpN = wid >> 1;
    const int m0 = blockIdx.y * 128;
    const int n0 = blockIdx.x * 128;
    const int row  = tid >> 1;
    const int half = tid & 1;

    // ldmatrix lane-address components
    const int a_lr = lane & 15;               // row within 16
    const int a_lc = (lane >> 4) << 2;        // uint32 col offset (0 or 4)
    const int b_lr = ((lane >> 4) << 3) + (lane & 7);   // row within 16 (two 8-blocks)
    const int b_lc = ((lane >> 3) & 1) << 2;  // uint32 col offset (0 or 4)

    const float* Arow = A + (size_t)(m0 + row) * Dc + half * 16;
    const float* Wrow = W + (size_t)(n0 + row) * Dc + half * 16;

    float acc[4][4][4];
    #pragma unroll
    for (int mt = 0; mt < 4; mt++)
        #pragma unroll
        for (int nt = 0; nt < 4; nt++)
            #pragma unroll
            for (int i = 0; i < 4; i++) acc[mt][nt][i] = 0.f;

    float4 pa[4], pw[4];
    #pragma unroll
    for (int j = 0; j < 4; j++) {
        pa[j] = *(const float4*)(Arow + j * 4);
        pw[j] = *(const float4*)(Wrow + j * 4);
    }
    // stage chunk 0 into buffer 0
    #pragma unroll
    for (int j = 0; j < 4; j++) {
        *(uint2*)&Au[0][row][half * 8 + j * 2] =
            make_uint2(pkbf2(pa[j].x, pa[j].y), pkbf2(pa[j].z, pa[j].w));
        *(uint2*)&Wu[0][row][half * 8 + j * 2] =
            make_uint2(pkbf2(pw[j].x, pw[j].y), pkbf2(pw[j].z, pw[j].w));
    }
    __syncthreads();

    int cur = 0;
    for (int k0 = 0; k0 < Dc; k0 += 32) {
        const bool more = (k0 + 32 < Dc);
        if (more) {
            #pragma unroll
            for (int j = 0; j < 4; j++) {
                pa[j] = *(const float4*)(Arow + k0 + 32 + j * 4);
                pw[j] = *(const float4*)(Wrow + k0 + 32 + j * 4);
            }
        }
        // ---- compute on buffer cur (ldmatrix + mma) ----
        #pragma unroll
        for (int ks = 0; ks < 2; ks++) {
            uint32_t af[4][4], bfr[2][4];
            #pragma unroll
            for (int mt = 0; mt < 4; mt++)
                ldsm_x4(af[mt], smem_u32(&Au[cur][warpM*64 + mt*16 + a_lr][ks*8 + a_lc]));
            #pragma unroll
            for (int ntp = 0; ntp < 2; ntp++)
                ldsm_x4(bfr[ntp], smem_u32(&Wu[cur][warpN*32 + ntp*16 + b_lr][ks*8 + b_lc]));
            #pragma unroll
            for (int mt = 0; mt < 4; mt++)
                #pragma unroll
                for (int nt = 0; nt < 4; nt++)
                    mma_bf16(acc[mt][nt], af[mt], bfr[nt>>1][(nt&1)*2], bfr[nt>>1][(nt&1)*2+1]);
        }
        // ---- stage next chunk into the other buffer ----
        if (more) {
            const int nxt = cur ^ 1;
            #pragma unroll
            for (int j = 0; j < 4; j++) {
                *(uint2*)&Au[nxt][row][half * 8 + j * 2] =
                    make_uint2(pkbf2(pa[j].x, pa[j].y), pkbf2(pa[j].z, pa[j].w));
                *(uint2*)&Wu[nxt][row][half * 8 + j * 2] =
                    make_uint2(pkbf2(pw[j].x, pw[j].y), pkbf2(pw[j].z, pw[j].w));
            }
        }
        __syncthreads();
        cur ^= 1;
    }

    // epilogue
    #pragma unroll
    for (int mt = 0; mt < 4; mt++) {
        const int mA = m0 + warpM * 64 + mt * 16 + g;
        #pragma unroll
        for (int nt = 0; nt < 4; nt++) {
            const int n = n0 + warpN * 32 + nt * 8 + 2 * tg;
            const float b0v = bias[n], b1v = bias[n + 1];
            #pragma unroll
            for (int rh = 0; rh < 2; rh++) {
                const int m = mA + rh * 8;
                float v0 = acc[mt][nt][rh * 2]     + b0v;
                float v1 = acc[mt][nt][rh * 2 + 1] + b1v;
                if (MODE == 0) {
                    const int bb = m >> 11;
                    const int l  = m & (Lc - 1);
                    const int h  = n >> 6;
                    const int d  = n & 63;
                    if (z == 2) {
                        float* base = &out[(((size_t)bb*Hc + h)*HDc + d)*Lc + l];
                        base[0]  = v0;
                        base[Lc] = v1;
                    } else {
                        *(float2*)&out[(((size_t)bb*Hc + h)*Lc + l)*HDc + d] =
                            make_float2(v0, v1);
                    }
                } else {
                    const float2 rr = *(const float2*)&residual[(size_t)m*Dc + n];
                    *(float2*)&out[(size_t)m*Dc + n] = make_float2(v0 + rr.x, v1 + rr.y);
                }
            }
        }
    }
}

// ============================================================
// Rotary + (cos,sin) table. One thread per (b,h,l) row.
// q pre-scaled by 0.125 (exact). phi layout: [B,L,H].
// ============================================================
__global__ __launch_bounds__(256)
void rotary_kernel(const float* __restrict__ phi)
{
    const int rest = blockIdx.x * blockDim.x + threadIdx.x;  // (b*H+h)*L + l
    if (rest >= BHL) return;
    const int l  = rest & (Lc - 1);
    const int bh = rest >> 11;
    const int h  = bh & (Hc - 1);
    const int b  = bh >> 4;

    const float p = phi[((size_t)b*Lc + l)*Hc + h];
    const float c = cosf(p);
    const float s = sinf(p);
    g_cs[rest] = make_float2(c, s);

    {
        float4* qp = (float4*)(g_q + (size_t)rest * HDc);
        float x[64];
        #pragma unroll
        for (int i = 0; i < 16; i++) *(float4*)&x[i*4] = qp[i];
        float r[64];
        #pragma unroll
        for (int d = 0; d < 32; d++) {
            r[d]      = (x[d] * c - x[d + 32] * s) * 0.125f;
            r[d + 32] = (x[d + 32] * c + x[d] * s) * 0.125f;
        }
        #pragma unroll
        for (int i = 0; i < 16; i++) qp[i] = *(float4*)&r[i*4];
    }
    {
        float4* kp = (float4*)(g_k + (size_t)rest * HDc);
        float x[64];
        #pragma unroll
        for (int i = 0; i < 16; i++) *(float4*)&x[i*4] = kp[i];
        float r[64];
        #pragma unroll
        for (int d = 0; d < 32; d++) {
            r[d]      = x[d] * c - x[d + 32] * s;
            r[d + 32] = x[d + 32] * c + x[d] * s;
        }
        #pragma unroll
        for (int i = 0; i < 16; i++) kp[i] = *(float4*)&r[i*4];
    }
}

// ============================================================
// bf16 tensor-core flash attention with ldmatrix fragment loads.
// grid (Lc/64, Hc, Bc), 128 thr = 4 warps, 16 q-rows per warp.
// Softmax / mask / normalization fully fp32.
// ============================================================
__global__ __launch_bounds__(128)
void attn_kernel(const float* __restrict__ amask)
{
    __shared__ uint32_t Ps[64][36];   // Q tile, then P tiles
    __shared__ uint32_t Ku[64][36];
    __shared__ uint32_t Vu[64][36];
    __shared__ float2 csk[64];
    __shared__ float  am[64];

    const int tid  = threadIdx.x;
    const int lane = tid & 31;
    const int warp = tid >> 5;
    const int g    = lane >> 2, tg = lane & 3;

    // ldmatrix lane-address components
    const int a_lr = lane & 15;
    const int a_lc = (lane >> 4) << 2;
    const int b_lr = ((lane >> 4) << 3) + (lane & 7);
    const int b_lc = ((lane >> 3) & 1) << 2;

    const int b  = blockIdx.z;
    const int h  = blockIdx.y;
    const int q0 = blockIdx.x * 64;
    const int bh = b * Hc + h;
    const size_t headoff = (size_t)bh * Lc * HDc;   // for g_q / g_k
    const size_t vtoff   = (size_t)bh * HDc * Lc;   // for g_vt
    const size_t bhL     = (size_t)bh * Lc;

    const int row  = tid >> 1;     // warp w stages rows 16w..16w+15
    const int half = tid & 1;

    // --- stage Q tile (bf16 pairs) into Ps ---
    {
        const float* src = g_q + headoff + (size_t)(q0 + row) * HDc + half * 32;
        #pragma unroll
        for (int j = 0; j < 8; j++) {
            float4 v = *(const float4*)(src + j * 4);
            *(uint2*)&Ps[row][half * 16 + j * 2] =
                make_uint2(pkbf2(v.x, v.y), pkbf2(v.z, v.w));
        }
    }
    __syncwarp();

    // --- per-warp Q A-fragments (registers, whole kernel) ---
    uint32_t qa[4][4];
    #pragma unroll
    for (int ks = 0; ks < 4; ks++)
        ldsm_x4(qa[ks], smem_u32(&Ps[warp*16 + a_lr][ks*8 + a_lc]));

    const int qrow = warp * 16 + g;
    const float2 csq0 = g_cs[bhL + q0 + qrow];
    const float2 csq1 = g_cs[bhL + q0 + qrow + 8];
    const int qg0 = q0 + qrow, qg1 = q0 + qrow + 8;
    __syncwarp();   // Ps (Q) consumed -> reusable for P

    float m0r = -3.4e38f, m1r = -3.4e38f;
    float l0r = 0.f, l1r = 0.f;
    float oacc[8][4];
    #pragma unroll
    for (int nt = 0; nt < 8; nt++)
        #pragma unroll
        for (int i = 0; i < 4; i++) oacc[nt][i] = 0.f;

    for (int kt = 0; kt < Lc; kt += 64) {
        __syncthreads();
        // --- stage K tile [key][hd] and V^T tile [d][key] as bf16 pairs ---
        {
            const float* ksrc = g_k  + headoff + (size_t)(kt + row) * HDc + half * 32;
            const float* vsrc = g_vt + vtoff   + (size_t)row * Lc + kt + half * 32;
            #pragma unroll
            for (int j = 0; j < 8; j++) {
                float4 kv = *(const float4*)(ksrc + j * 4);
                float4 vv = *(const float4*)(vsrc + j * 4);
                *(uint2*)&Ku[row][half * 16 + j * 2] =
                    make_uint2(pkbf2(kv.x, kv.y), pkbf2(kv.z, kv.w));
                *(uint2*)&Vu[row][half * 16 + j * 2] =
                    make_uint2(pkbf2(vv.x, vv.y), pkbf2(vv.z, vv.w));
            }
        }
        if (tid < 64) {
            csk[tid] = g_cs[bhL + kt + tid];
            am[tid]  = amask[(size_t)b * Lc + kt + tid];
        }
        __syncthreads();

        // --- scores: S[16 x 64] per warp ---
        float sacc[8][4];
        #pragma unroll
        for (int nt = 0; nt < 8; nt++)
            #pragma unroll
            for (int i = 0; i < 4; i++) sacc[nt][i] = 0.f;
        #pragma unroll
        for (int ks = 0; ks < 4; ks++) {
            #pragma unroll
            for (int ntp = 0; ntp < 4; ntp++) {
                uint32_t kb4[4];
                ldsm_x4(kb4, smem_u32(&Ku[ntp*16 + b_lr][ks*8 + b_lc]));
                mma_bf16(sacc[2*ntp],     qa[ks], kb4[0], kb4[1]);
                mma_bf16(sacc[2*ntp + 1], qa[ks], kb4[2], kb4[3]);
            }
        }

        // --- mask + online softmax (fp32, exact reference semantics) ---
        float cmax0 = -3.4e38f, cmax1 = -3.4e38f;
        #pragma unroll
        for (int nt = 0; nt < 8; nt++) {
            const int c0 = nt * 8 + 2 * tg;
            const float2 ck0 = csk[c0], ck1 = csk[c0 + 1];
            const float a0 = am[c0], a1 = am[c0 + 1];
            const int kg0 = kt + c0, kg1 = kt + c0 + 1;

            float dc;
            dc = fmaf(csq0.x, ck0.x, csq0.y * ck0.y);
            if (dc < -0.7f && kg0 != qg0) sacc[nt][0] = -1e9f;
            dc = fmaf(csq0.x, ck1.x, csq0.y * ck1.y);
            if (dc < -0.7f && kg1 != qg0) sacc[nt][1] = -1e9f;
            dc = fmaf(csq1.x, ck0.x, csq1.y * ck0.y);
            if (dc < -0.7f && kg0 != qg1) sacc[nt][2] = -1e9f;
            dc = fmaf(csq1.x, ck1.x, csq1.y * ck1.y);
            if (dc < -0.7f && kg1 != qg1) sacc[nt][3] = -1e9f;

            sacc[nt][0] += a0; sacc[nt][1] += a1;
            sacc[nt][2] += a0; sacc[nt][3] += a1;
            cmax0 = fmaxf(cmax0, fmaxf(sacc[nt][0], sacc[nt][1]));
            cmax1 = fmaxf(cmax1, fmaxf(sacc[nt][2], sacc[nt][3]));
        }
        cmax0 = fmaxf(cmax0, __shfl_xor_sync(0xffffffffu, cmax0, 1));
        cmax0 = fmaxf(cmax0, __shfl_xor_sync(0xffffffffu, cmax0, 2));
        cmax1 = fmaxf(cmax1, __shfl_xor_sync(0xffffffffu, cmax1, 1));
        cmax1 = fmaxf(cmax1, __shfl_xor_sync(0xffffffffu, cmax1, 2));

        if (cmax0 > m0r) {
            const float corr = __expf(m0r - cmax0);
            m0r = cmax0; l0r *= corr;
            #pragma unroll
            for (int nt = 0; nt < 8; nt++) { oacc[nt][0] *= corr; oacc[nt][1] *= corr; }
        }
        if (cmax1 > m1r) {
            const float corr = __expf(m1r - cmax1);
            m1r = cmax1; l1r *= corr;
            #pragma unroll
            for (int nt = 0; nt < 8; nt++) { oacc[nt][2] *= corr; oacc[nt][3] *= corr; }
        }

        #pragma unroll
        for (int nt = 0; nt < 8; nt++) {
            float p00 = __expf(sacc[nt][0] - m0r);
            float p01 = __expf(sacc[nt][1] - m0r);
            float p10 = __expf(sacc[nt][2] - m1r);
            float p11 = __expf(sacc[nt][3] - m1r);
            l0r += p00 + p01;
            l1r += p10 + p11;
            Ps[qrow    ][nt * 4 + tg] = pkbf2(p00, p01);
            Ps[qrow + 8][nt * 4 + tg] = pkbf2(p10, p11);
        }
        __syncwarp();

        // --- PV: O += P @ V  (A = P bf16, B = V^T bf16) ---
        #pragma unroll
        for (int ks = 0; ks < 4; ks++) {
            uint32_t pa[4];
            ldsm_x4(pa, smem_u32(&Ps[warp*16 + a_lr][ks*8 + a_lc]));
            #pragma unroll
            for (int ntp = 0; ntp < 4; ntp++) {
                uint32_t vb4[4];
                ldsm_x4(vb4, smem_u32(&Vu[ntp*16 + b_lr][ks*8 + b_lc]));
                mma_bf16(oacc[2*ntp],     pa, vb4[0], vb4[1]);
                mma_bf16(oacc[2*ntp + 1], pa, vb4[2], vb4[3]);
            }
        }
        __syncwarp();
    }

    // --- finalize ---
    l0r += __shfl_xor_sync(0xffffffffu, l0r, 1);
    l0r += __shfl_xor_sync(0xffffffffu, l0r, 2);
    l1r += __shfl_xor_sync(0xffffffffu, l1r, 1);
    l1r += __shfl_xor_sync(0xffffffffu, l1r, 2);
    const float inv0 = 1.f / l0r;
    const float inv1 = 1.f / l1r;

    float* c0p = g_ctx + ((size_t)(b * Lc + qg0)) * Dc + h * HDc;
    float* c1p = g_ctx + ((size_t)(b * Lc + qg1)) * Dc + h * HDc;
    #pragma unroll
    for (int nt = 0; nt < 8; nt++) {
        const int d = nt * 8 + 2 * tg;
        *(float2*)&c0p[d] = make_float2(oacc[nt][0] * inv0, oacc[nt][1] * inv0);
        *(float2*)&c1p[d] = make_float2(oacc[nt][2] * inv1, oacc[nt][3] * inv1);
    }
}

// ============================================================
// LayerNorm over last dim (1024). one block per row, 256 threads.
// ============================================================
__global__ __launch_bounds__(256)
void ln_kernel(const float* __restrict__ gamma, const float* __restrict__ beta,
               float* __restrict__ out)
{
    const int row = blockIdx.x;
    const int tid = threadIdx.x;
    const float4 v = ((const float4*)(g_x + (size_t)row * Dc))[tid];
    float s  = v.x + v.y + v.z + v.w;
    float sq = v.x*v.x + v.y*v.y + v.z*v.z + v.w*v.w;
    #pragma unroll
    for (int off = 16; off > 0; off >>= 1) {
        s  += __shfl_xor_sync(0xffffffffu, s,  off);
        sq += __shfl_xor_sync(0xffffffffu, sq, off);
    }
    __shared__ float ssum[8], ssq[8];
    const int w = tid >> 5;
    if ((tid & 31) == 0) { ssum[w] = s; ssq[w] = sq; }
    __syncthreads();
    if (tid == 0) {
        float ts = 0.f, tq = 0.f;
        #pragma unroll
        for (int i = 0; i < 8; i++) { ts += ssum[i]; tq += ssq[i]; }
        ssum[0] = ts; ssq[0] = tq;
    }
    __syncthreads();
    const float mean = ssum[0] * (1.f / Dc);
    const float var  = ssq[0]  * (1.f / Dc) - mean * mean;
    const float inv  = rsqrtf(var + 1e-12f);
    const float4 gv = ((const float4*)gamma)[tid];
    const float4 bv = ((const float4*)beta)[tid];
    float4 ov;
    ov.x = (v.x - mean) * inv * gv.x + bv.x;
    ov.y = (v.y - mean) * inv * gv.y + bv.y;
    ov.z = (v.z - mean) * inv * gv.z + bv.z;
    ov.w = (v.w - mean) * inv * gv.w + bv.w;
    ((float4*)out)[(size_t)row * (Dc/4) + tid] = ov;
}

// ============================================================
// launch
// ============================================================
extern "C" void kernel_launch(void* const* d_in, const int* in_sizes, int n_in,
                              void* d_out, int out_size)
{
    const float* hs    = (const float*)d_in[0];
    const float* amask = (const float*)d_in[1];
    const float* phi   = (const float*)d_in[2];
    const float* Wq    = (const float*)d_in[3];
    const float* bq    = (const float*)d_in[4];
    const float* Wk    = (const float*)d_in[5];
    const float* bk    = (const float*)d_in[6];
    const float* Wv    = (const float*)d_in[7];
    const float* bv    = (const float*)d_in[8];
    const float* Wo    = (const float*)d_in[9];
    const float* bo    = (const float*)d_in[10];
    const float* lng   = (const float*)d_in[11];
    const float* lnb   = (const float*)d_in[12];
    float* out = (float*)d_out;

    // 1) QKV projections -> g_q/g_k ([B,H,L,HD]) and g_vt ([B,H,HD,L])
    dim3 g0(Dc/128, Mtot/128, 3);
    gemm_kernel<0><<<g0, 256>>>(hs, Wq, bq, Wk, bk, Wv, bv, nullptr);

    // 2) rotary (in place, q pre-scaled) + (cos,sin) table
    rotary_kernel<<<BHL/256, 256>>>(phi);

    // 3) attention -> g_ctx [B,L,D]
    dim3 g2(Lc/64, Hc, Bc);
    attn_kernel<<<g2, 128>>>(amask);

    // 4) output projection + residual -> g_x
    dim3 g3(Dc/128, Mtot/128, 1);
    gemm_kernel<1><<<g3, 256>>>(nullptr, Wo, bo, nullptr, nullptr, nullptr, nullptr, hs);

    // 5) layernorm -> d_out
    ln_kernel<<<Mtot, 256>>>(lng, lnb, out);
}

// round 11
// speedup vs baseline: 1.8218x; 1.8218x over previous
#include <cuda_runtime.h>
#include <cuda_bf16.h>
#include <math.h>
#include <stdint.h>

// Problem constants
#define Bc   2
#define Lc   2048
#define Dc   1024
#define Hc   16
#define HDc  64
#define Mtot (Bc*Lc)      // 4096
#define BHL  (Bc*Hc*Lc)   // 65536

// ---- scratch (device globals: allocation-free, graph-capturable) ----
__device__ float  g_q[(size_t)BHL*HDc];      // fp32 QKV-gemm out (pre-rotary)
__device__ float  g_k[(size_t)BHL*HDc];
__device__ float  g_x[(size_t)Mtot*Dc];      // pre-LN
__device__ float2 g_cs[BHL];                 // (cos phi, sin phi)
// packed bf16 operand tensors (16B aligned via uint4)
__device__ uint4  g_qh[(size_t)BHL*HDc/8];   // [bh][l][hd/2 u32] (q*0.125, rotated)
__device__ uint4  g_kh[(size_t)BHL*HDc/8];   // [bh][l][hd/2 u32]
__device__ uint4  g_vth[(size_t)BHL*HDc/8];  // [bh][d][Lc/2 u32] (V transposed)
__device__ uint4  g_ctxh[(size_t)Mtot*Dc/8]; // [B,L,D/2 u32]

// ---- helpers ----
__device__ __forceinline__ uint32_t pkbf2(float lo, float hi) {
    __nv_bfloat162 h = __float22bfloat162_rn(make_float2(lo, hi));
    return *(uint32_t*)&h;
}
__device__ __forceinline__ void mma_bf16(float* c, const uint32_t* a,
                                         uint32_t b0, uint32_t b1)
{
    asm volatile(
        "mma.sync.aligned.m16n8k16.row.col.f32.bf16.bf16.f32 "
        "{%0,%1,%2,%3}, {%4,%5,%6,%7}, {%8,%9}, {%0,%1,%2,%3};"
        : "+f"(c[0]), "+f"(c[1]), "+f"(c[2]), "+f"(c[3])
        : "r"(a[0]), "r"(a[1]), "r"(a[2]), "r"(a[3]), "r"(b0), "r"(b1));
}
__device__ __forceinline__ uint32_t smem_u32(const void* p) {
    return (uint32_t)__cvta_generic_to_shared(p);
}
__device__ __forceinline__ void ldsm_x4(uint32_t* r, uint32_t addr) {
    asm volatile("ldmatrix.sync.aligned.m8n8.x4.shared.b16 {%0,%1,%2,%3}, [%4];"
                 : "=r"(r[0]), "=r"(r[1]), "=r"(r[2]), "=r"(r[3]) : "r"(addr));
}
__device__ __forceinline__ void cpa16(uint32_t dst, const void* src) {
    asm volatile("cp.async.ca.shared.global [%0], [%1], 16;\n" :: "r"(dst), "l"(src));
}

// ============================================================
// bf16 tile GEMM (ldmatrix + double-buffered smem).
// MODE 0: A = fp32 hidden_states; z in {0,1,2} -> Wq/Wk/Wv;
//         z<2 writes fp32 g_q/g_k [bh][l][hd]; z==2 writes bf16 g_vth [bh][d][l].
// MODE 1: A = bf16 packed g_ctxh (staged without conversion);
//         out = g_x = ctx@Wo^T + bo + residual (fp32).
// ============================================================
template<int MODE>
__global__ __launch_bounds__(256)
void gemm_kernel(const float* __restrict__ Ain,
                 const float* __restrict__ W0, const float* __restrict__ bias0,
                 const float* __restrict__ W1, const float* __restrict__ bias1,
                 const float* __restrict__ W2, const float* __restrict__ bias2,
                 const float* __restrict__ residual)
{
    const float* A; const float* W; const float* bias;
    const int z = (MODE == 0) ? blockIdx.z : 0;
    if (MODE == 0) {
        A = Ain;
        W    = (z == 0) ? W0    : (z == 1) ? W1    : W2;
        bias = (z == 0) ? bias0 : (z == 1) ? bias1 : bias2;
    } else {
        A = nullptr; W = W0; bias = bias0;
    }

    __shared__ uint32_t Au[2][128][20];
    __shared__ uint32_t Wu[2][128][20];

    const int tid  = threadIdx.x;
    const int lane = tid & 31;
    const int wid  = tid >> 5;
    const int g    = lane >> 2, tg = lane & 3;
    const int warpM = wid & 1, warpN = wid >> 1;
    const int m0 = blockIdx.y * 128;
    const int n0 = blockIdx.x * 128;
    const int row  = tid >> 1;
    const int half = tid & 1;

    const int a_lr = lane & 15;
    const int a_lc = (lane >> 4) << 2;
    const int b_lr = ((lane >> 4) << 3) + (lane & 7);
    const int b_lc = ((lane >> 3) & 1) << 2;

    const float*    Arow = (MODE == 0) ? (A + (size_t)(m0 + row) * Dc + half * 16) : nullptr;
    const uint32_t* Crow = (MODE == 1)
        ? ((const uint32_t*)g_ctxh + (size_t)(m0 + row) * (Dc/2) + half * 8) : nullptr;
    const float* Wrow = W + (size_t)(n0 + row) * Dc + half * 16;

    float acc[4][4][4];
    #pragma unroll
    for (int mt = 0; mt < 4; mt++)
        #pragma unroll
        for (int nt = 0; nt < 4; nt++)
            #pragma unroll
            for (int i = 0; i < 4; i++) acc[mt][nt][i] = 0.f;

    float4 pa[4], pw[4];
    uint4  pc[2];
    if (MODE == 0) {
        #pragma unroll
        for (int j = 0; j < 4; j++) pa[j] = *(const float4*)(Arow + j * 4);
    } else {
        pc[0] = *(const uint4*)(Crow);
        pc[1] = *(const uint4*)(Crow + 4);
    }
    #pragma unroll
    for (int j = 0; j < 4; j++) pw[j] = *(const float4*)(Wrow + j * 4);

    // stage chunk 0 into buffer 0
    if (MODE == 0) {
        #pragma unroll
        for (int j = 0; j < 4; j++)
            *(uint2*)&Au[0][row][half * 8 + j * 2] =
                make_uint2(pkbf2(pa[j].x, pa[j].y), pkbf2(pa[j].z, pa[j].w));
    } else {
        *(uint4*)&Au[0][row][half * 8]     = pc[0];
        *(uint4*)&Au[0][row][half * 8 + 4] = pc[1];
    }
    #pragma unroll
    for (int j = 0; j < 4; j++)
        *(uint2*)&Wu[0][row][half * 8 + j * 2] =
            make_uint2(pkbf2(pw[j].x, pw[j].y), pkbf2(pw[j].z, pw[j].w));
    __syncthreads();

    int cur = 0;
    for (int k0 = 0; k0 < Dc; k0 += 32) {
        const bool more = (k0 + 32 < Dc);
        if (more) {
            if (MODE == 0) {
                #pragma unroll
                for (int j = 0; j < 4; j++)
                    pa[j] = *(const float4*)(Arow + k0 + 32 + j * 4);
            } else {
                pc[0] = *(const uint4*)(Crow + ((k0 + 32) >> 1));
                pc[1] = *(const uint4*)(Crow + ((k0 + 32) >> 1) + 4);
            }
            #pragma unroll
            for (int j = 0; j < 4; j++)
                pw[j] = *(const float4*)(Wrow + k0 + 32 + j * 4);
        }
        // ---- compute on buffer cur ----
        #pragma unroll
        for (int ks = 0; ks < 2; ks++) {
            uint32_t af[4][4], bfr[2][4];
            #pragma unroll
            for (int mt = 0; mt < 4; mt++)
                ldsm_x4(af[mt], smem_u32(&Au[cur][warpM*64 + mt*16 + a_lr][ks*8 + a_lc]));
            #pragma unroll
            for (int ntp = 0; ntp < 2; ntp++)
                ldsm_x4(bfr[ntp], smem_u32(&Wu[cur][warpN*32 + ntp*16 + b_lr][ks*8 + b_lc]));
            #pragma unroll
            for (int mt = 0; mt < 4; mt++)
                #pragma unroll
                for (int nt = 0; nt < 4; nt++)
                    mma_bf16(acc[mt][nt], af[mt], bfr[nt>>1][(nt&1)*2], bfr[nt>>1][(nt&1)*2+1]);
        }
        // ---- stage next chunk ----
        if (more) {
            const int nxt = cur ^ 1;
            if (MODE == 0) {
                #pragma unroll
                for (int j = 0; j < 4; j++)
                    *(uint2*)&Au[nxt][row][half * 8 + j * 2] =
                        make_uint2(pkbf2(pa[j].x, pa[j].y), pkbf2(pa[j].z, pa[j].w));
            } else {
                *(uint4*)&Au[nxt][row][half * 8]     = pc[0];
                *(uint4*)&Au[nxt][row][half * 8 + 4] = pc[1];
            }
            #pragma unroll
            for (int j = 0; j < 4; j++)
                *(uint2*)&Wu[nxt][row][half * 8 + j * 2] =
                    make_uint2(pkbf2(pw[j].x, pw[j].y), pkbf2(pw[j].z, pw[j].w));
        }
        __syncthreads();
        cur ^= 1;
    }

    // epilogue
    #pragma unroll
    for (int mt = 0; mt < 4; mt++) {
        const int mA = m0 + warpM * 64 + mt * 16 + g;
        #pragma unroll
        for (int nt = 0; nt < 4; nt++) {
            const int n = n0 + warpN * 32 + nt * 8 + 2 * tg;
            const float b0v = bias[n], b1v = bias[n + 1];
            #pragma unroll
            for (int rh = 0; rh < 2; rh++) {
                const int m = mA + rh * 8;
                float v0 = acc[mt][nt][rh * 2]     + b0v;
                float v1 = acc[mt][nt][rh * 2 + 1] + b1v;
                if (MODE == 0) {
                    const int bb = m >> 11;
                    const int l  = m & (Lc - 1);
                    const int h  = n >> 6;
                    const int d  = n & 63;
                    if (z == 2) {
                        // V transposed bf16: [bh][d][l]
                        __nv_bfloat16* vb = (__nv_bfloat16*)g_vth +
                            (((size_t)bb*Hc + h)*HDc + d)*Lc + l;
                        vb[0]  = __float2bfloat16_rn(v0);
                        vb[Lc] = __float2bfloat16_rn(v1);
                    } else {
                        float* out = (z == 0) ? g_q : g_k;
                        *(float2*)&out[(((size_t)bb*Hc + h)*Lc + l)*HDc + d] =
                            make_float2(v0, v1);
                    }
                } else {
                    const float2 rr = *(const float2*)&residual[(size_t)m*Dc + n];
                    *(float2*)&g_x[(size_t)m*Dc + n] = make_float2(v0 + rr.x, v1 + rr.y);
                }
            }
        }
    }
}

// ============================================================
// Rotary: fp32 in (g_q/g_k), packed-bf16 out (g_qh/g_kh) + cos/sin table.
// q pre-scaled by 0.125 (exact pow2 -> commutes with bf16 rounding).
// ============================================================
__global__ __launch_bounds__(256)
void rotary_kernel(const float* __restrict__ phi)
{
    const int rest = blockIdx.x * blockDim.x + threadIdx.x;  // (b*H+h)*L + l
    if (rest >= BHL) return;
    const int l  = rest & (Lc - 1);
    const int bh = rest >> 11;
    const int h  = bh & (Hc - 1);
    const int b  = bh >> 4;

    const float p = phi[((size_t)b*Lc + l)*Hc + h];
    const float c = cosf(p);
    const float s = sinf(p);
    g_cs[rest] = make_float2(c, s);

    {
        const float4* qp = (const float4*)(g_q + (size_t)rest * HDc);
        float x[64];
        #pragma unroll
        for (int i = 0; i < 16; i++) *(float4*)&x[i*4] = qp[i];
        float r[64];
        #pragma unroll
        for (int d = 0; d < 32; d++) {
            r[d]      = (x[d] * c - x[d + 32] * s) * 0.125f;
            r[d + 32] = (x[d + 32] * c + x[d] * s) * 0.125f;
        }
        uint32_t* qd = (uint32_t*)g_qh + (size_t)rest * 32;
        #pragma unroll
        for (int i = 0; i < 32; i++) qd[i] = pkbf2(r[2*i], r[2*i + 1]);
    }
    {
        const float4* kp = (const float4*)(g_k + (size_t)rest * HDc);
        float x[64];
        #pragma unroll
        for (int i = 0; i < 16; i++) *(float4*)&x[i*4] = kp[i];
        float r[64];
        #pragma unroll
        for (int d = 0; d < 32; d++) {
            r[d]      = x[d] * c - x[d + 32] * s;
            r[d + 32] = x[d + 32] * c + x[d] * s;
        }
        uint32_t* kd = (uint32_t*)g_kh + (size_t)rest * 32;
        #pragma unroll
        for (int i = 0; i < 32; i++) kd[i] = pkbf2(r[2*i], r[2*i + 1]);
    }
}

// ============================================================
// bf16 tensor-core flash attention: cp.async double-buffered K/V,
// ldmatrix fragments, fp32 softmax/mask. grid (Lc/64, Hc, Bc), 128 thr.
// ============================================================
__global__ __launch_bounds__(128)
void attn_kernel(const float* __restrict__ amask)
{
    __shared__ uint32_t Ps[64][36];      // Q tile, then P tiles (per-warp rows)
    __shared__ uint32_t Ku[2][64][36];
    __shared__ uint32_t Vu[2][64][36];
    __shared__ float2 csk[2][64];
    __shared__ float  am[2][64];

    const int tid  = threadIdx.x;
    const int lane = tid & 31;
    const int warp = tid >> 5;
    const int g    = lane >> 2, tg = lane & 3;

    const int a_lr = lane & 15;
    const int a_lc = (lane >> 4) << 2;
    const int b_lr = ((lane >> 4) << 3) + (lane & 7);
    const int b_lc = ((lane >> 3) & 1) << 2;

    const int b  = blockIdx.z;
    const int h  = blockIdx.y;
    const int q0 = blockIdx.x * 64;
    const int bh = b * Hc + h;
    const size_t bhL = (size_t)bh * Lc;

    const uint32_t* qb = (const uint32_t*)g_qh  + bhL * 32;           // [l][32]
    const uint32_t* kb = (const uint32_t*)g_kh  + bhL * 32;           // [l][32]
    const uint32_t* vb = (const uint32_t*)g_vth + (size_t)bh * HDc * (Lc/2); // [d][Lc/2]

    const int row  = tid >> 1;     // warp w stages rows 16w..16w+15
    const int half = tid & 1;

    // --- stage Q tile (already bf16) ---
    {
        const uint32_t* src = qb + (size_t)(q0 + row) * 32 + half * 16;
        *(uint4*)&Ps[row][half * 16]      = *(const uint4*)(src);
        *(uint4*)&Ps[row][half * 16 + 4]  = *(const uint4*)(src + 4);
        *(uint4*)&Ps[row][half * 16 + 8]  = *(const uint4*)(src + 8);
        *(uint4*)&Ps[row][half * 16 + 12] = *(const uint4*)(src + 12);
    }
    __syncwarp();

    uint32_t qa[4][4];
    #pragma unroll
    for (int ks = 0; ks < 4; ks++)
        ldsm_x4(qa[ks], smem_u32(&Ps[warp*16 + a_lr][ks*8 + a_lc]));

    const int qrow = warp * 16 + g;
    const float2 csq0 = g_cs[bhL + q0 + qrow];
    const float2 csq1 = g_cs[bhL + q0 + qrow + 8];
    const int qg0 = q0 + qrow, qg1 = q0 + qrow + 8;
    __syncwarp();   // Ps (Q) consumed -> reusable for P

    // --- cp.async stage of a K/V tile: 4 16B chunks per thread per matrix ---
#define STAGE_KV(kt_, buf_) do {                                              \
        _Pragma("unroll")                                                     \
        for (int i_ = 0; i_ < 4; i_++) {                                      \
            const int c_ = tid + i_ * 128;                                    \
            const int r_ = c_ >> 3, c4_ = (c_ & 7) * 4;                       \
            cpa16(smem_u32(&Ku[buf_][r_][c4_]),                               \
                  kb + (size_t)((kt_) + r_) * 32 + c4_);                      \
            cpa16(smem_u32(&Vu[buf_][r_][c4_]),                               \
                  vb + (size_t)r_ * (Lc/2) + ((kt_) >> 1) + c4_);             \
        }                                                                     \
        asm volatile("cp.async.commit_group;\n" ::);                          \
    } while (0)
#define STAGE_CSAM(kt_, buf_) do {                                            \
        if (tid < 64) {                                                       \
            csk[buf_][tid] = g_cs[bhL + (kt_) + tid];                         \
            am[buf_][tid]  = amask[(size_t)b * Lc + (kt_) + tid];             \
        }                                                                     \
    } while (0)

    // prologue: tile 0
    STAGE_KV(0, 0);
    STAGE_CSAM(0, 0);
    asm volatile("cp.async.wait_group 0;\n" ::);
    __syncthreads();

    float m0r = -3.4e38f, m1r = -3.4e38f;
    float l0r = 0.f, l1r = 0.f;
    float oacc[8][4];
    #pragma unroll
    for (int nt = 0; nt < 8; nt++)
        #pragma unroll
        for (int i = 0; i < 4; i++) oacc[nt][i] = 0.f;

    int cur = 0;
    for (int kt = 0; kt < Lc; kt += 64) {
        const bool more = (kt + 64 < Lc);
        if (more) {                          // prefetch next tile (overlaps compute)
            STAGE_KV(kt + 64, cur ^ 1);
            STAGE_CSAM(kt + 64, cur ^ 1);
        }

        // --- scores: S[16 x 64] per warp ---
        float sacc[8][4];
        #pragma unroll
        for (int nt = 0; nt < 8; nt++)
            #pragma unroll
            for (int i = 0; i < 4; i++) sacc[nt][i] = 0.f;
        #pragma unroll
        for (int ks = 0; ks < 4; ks++) {
            #pragma unroll
            for (int ntp = 0; ntp < 4; ntp++) {
                uint32_t kb4[4];
                ldsm_x4(kb4, smem_u32(&Ku[cur][ntp*16 + b_lr][ks*8 + b_lc]));
                mma_bf16(sacc[2*ntp],     qa[ks], kb4[0], kb4[1]);
                mma_bf16(sacc[2*ntp + 1], qa[ks], kb4[2], kb4[3]);
            }
        }

        // --- mask + online softmax (fp32, exact reference semantics) ---
        float cmax0 = -3.4e38f, cmax1 = -3.4e38f;
        #pragma unroll
        for (int nt = 0; nt < 8; nt++) {
            const int c0 = nt * 8 + 2 * tg;
            const float2 ck0 = csk[cur][c0], ck1 = csk[cur][c0 + 1];
            const float a0 = am[cur][c0], a1 = am[cur][c0 + 1];
            const int kg0 = kt + c0, kg1 = kt + c0 + 1;

            float dc;
            dc = fmaf(csq0.x, ck0.x, csq0.y * ck0.y);
            if (dc < -0.7f && kg0 != qg0) sacc[nt][0] = -1e9f;
            dc = fmaf(csq0.x, ck1.x, csq0.y * ck1.y);
            if (dc < -0.7f && kg1 != qg0) sacc[nt][1] = -1e9f;
            dc = fmaf(csq1.x, ck0.x, csq1.y * ck0.y);
            if (dc < -0.7f && kg0 != qg1) sacc[nt][2] = -1e9f;
            dc = fmaf(csq1.x, ck1.x, csq1.y * ck1.y);
            if (dc < -0.7f && kg1 != qg1) sacc[nt][3] = -1e9f;

            sacc[nt][0] += a0; sacc[nt][1] += a1;
            sacc[nt][2] += a0; sacc[nt][3] += a1;
            cmax0 = fmaxf(cmax0, fmaxf(sacc[nt][0], sacc[nt][1]));
            cmax1 = fmaxf(cmax1, fmaxf(sacc[nt][2], sacc[nt][3]));
        }
        cmax0 = fmaxf(cmax0, __shfl_xor_sync(0xffffffffu, cmax0, 1));
        cmax0 = fmaxf(cmax0, __shfl_xor_sync(0xffffffffu, cmax0, 2));
        cmax1 = fmaxf(cmax1, __shfl_xor_sync(0xffffffffu, cmax1, 1));
        cmax1 = fmaxf(cmax1, __shfl_xor_sync(0xffffffffu, cmax1, 2));

        if (cmax0 > m0r) {
            const float corr = __expf(m0r - cmax0);
            m0r = cmax0; l0r *= corr;
            #pragma unroll
            for (int nt = 0; nt < 8; nt++) { oacc[nt][0] *= corr; oacc[nt][1] *= corr; }
        }
        if (cmax1 > m1r) {
            const float corr = __expf(m1r - cmax1);
            m1r = cmax1; l1r *= corr;
            #pragma unroll
            for (int nt = 0; nt < 8; nt++) { oacc[nt][2] *= corr; oacc[nt][3] *= corr; }
        }

        #pragma unroll
        for (int nt = 0; nt < 8; nt++) {
            float p00 = __expf(sacc[nt][0] - m0r);
            float p01 = __expf(sacc[nt][1] - m0r);
            float p10 = __expf(sacc[nt][2] - m1r);
            float p11 = __expf(sacc[nt][3] - m1r);
            l0r += p00 + p01;
            l1r += p10 + p11;
            Ps[qrow    ][nt * 4 + tg] = pkbf2(p00, p01);
            Ps[qrow + 8][nt * 4 + tg] = pkbf2(p10, p11);
        }
        __syncwarp();

        // --- PV: O += P @ V ---
        #pragma unroll
        for (int ks = 0; ks < 4; ks++) {
            uint32_t pa[4];
            ldsm_x4(pa, smem_u32(&Ps[warp*16 + a_lr][ks*8 + a_lc]));
            #pragma unroll
            for (int ntp = 0; ntp < 4; ntp++) {
                uint32_t vb4[4];
                ldsm_x4(vb4, smem_u32(&Vu[cur][ntp*16 + b_lr][ks*8 + b_lc]));
                mma_bf16(oacc[2*ntp],     pa, vb4[0], vb4[1]);
                mma_bf16(oacc[2*ntp + 1], pa, vb4[2], vb4[3]);
            }
        }

        if (more) asm volatile("cp.async.wait_group 0;\n" ::);
        __syncthreads();
        cur ^= 1;
    }

    // --- finalize: write ctx as packed bf16 ---
    l0r += __shfl_xor_sync(0xffffffffu, l0r, 1);
    l0r += __shfl_xor_sync(0xffffffffu, l0r, 2);
    l1r += __shfl_xor_sync(0xffffffffu, l1r, 1);
    l1r += __shfl_xor_sync(0xffffffffu, l1r, 2);
    const float inv0 = 1.f / l0r;
    const float inv1 = 1.f / l1r;

    uint32_t* ctxu = (uint32_t*)g_ctxh;
    const size_t base0 = ((size_t)(b * Lc + qg0) * Dc + h * HDc) >> 1;
    const size_t base1 = ((size_t)(b * Lc + qg1) * Dc + h * HDc) >> 1;
    #pragma unroll
    for (int nt = 0; nt < 8; nt++) {
        const int d = nt * 8 + 2 * tg;
        ctxu[base0 + (d >> 1)] = pkbf2(oacc[nt][0] * inv0, oacc[nt][1] * inv0);
        ctxu[base1 + (d >> 1)] = pkbf2(oacc[nt][2] * inv1, oacc[nt][3] * inv1);
    }
#undef STAGE_KV
#undef STAGE_CSAM
}

// ============================================================
// LayerNorm over last dim (1024). one block per row, 256 threads.
// ============================================================
__global__ __launch_bounds__(256)
void ln_kernel(const float* __restrict__ gamma, const float* __restrict__ beta,
               float* __restrict__ out)
{
    const int row = blockIdx.x;
    const int tid = threadIdx.x;
    const float4 v = ((const float4*)(g_x + (size_t)row * Dc))[tid];
    float s  = v.x + v.y + v.z + v.w;
    float sq = v.x*v.x + v.y*v.y + v.z*v.z + v.w*v.w;
    #pragma unroll
    for (int off = 16; off > 0; off >>= 1) {
        s  += __shfl_xor_sync(0xffffffffu, s,  off);
        sq += __shfl_xor_sync(0xffffffffu, sq, off);
    }
    __shared__ float ssum[8], ssq[8];
    const int w = tid >> 5;
    if ((tid & 31) == 0) { ssum[w] = s; ssq[w] = sq; }
    __syncthreads();
    if (tid == 0) {
        float ts = 0.f, tq = 0.f;
        #pragma unroll
        for (int i = 0; i < 8; i++) { ts += ssum[i]; tq += ssq[i]; }
        ssum[0] = ts; ssq[0] = tq;
    }
    __syncthreads();
    const float mean = ssum[0] * (1.f / Dc);
    const float var  = ssq[0]  * (1.f / Dc) - mean * mean;
    const float inv  = rsqrtf(var + 1e-12f);
    const float4 gv = ((const float4*)gamma)[tid];
    const float4 bv = ((const float4*)beta)[tid];
    float4 ov;
    ov.x = (v.x - mean) * inv * gv.x + bv.x;
    ov.y = (v.y - mean) * inv * gv.y + bv.y;
    ov.z = (v.z - mean) * inv * gv.z + bv.z;
    ov.w = (v.w - mean) * inv * gv.w + bv.w;
    ((float4*)out)[(size_t)row * (Dc/4) + tid] = ov;
}

// ============================================================
// launch
// ============================================================
extern "C" void kernel_launch(void* const* d_in, const int* in_sizes, int n_in,
                              void* d_out, int out_size)
{
    const float* hs    = (const float*)d_in[0];
    const float* amask = (const float*)d_in[1];
    const float* phi   = (const float*)d_in[2];
    const float* Wq    = (const float*)d_in[3];
    const float* bq    = (const float*)d_in[4];
    const float* Wk    = (const float*)d_in[5];
    const float* bk    = (const float*)d_in[6];
    const float* Wv    = (const float*)d_in[7];
    const float* bv    = (const float*)d_in[8];
    const float* Wo    = (const float*)d_in[9];
    const float* bo    = (const float*)d_in[10];
    const float* lng   = (const float*)d_in[11];
    const float* lnb   = (const float*)d_in[12];
    float* out = (float*)d_out;

    // 1) QKV projections -> g_q/g_k fp32, g_vth bf16 (transposed)
    dim3 g0(Dc/128, Mtot/128, 3);
    gemm_kernel<0><<<g0, 256>>>(hs, Wq, bq, Wk, bk, Wv, bv, nullptr);

    // 2) rotary -> g_qh/g_kh packed bf16 + cos/sin table
    rotary_kernel<<<BHL/256, 256>>>(phi);

    // 3) attention -> g_ctxh packed bf16
    dim3 g2(Lc/64, Hc, Bc);
    attn_kernel<<<g2, 128>>>(amask);

    // 4) output projection + residual -> g_x
    dim3 g3(Dc/128, Mtot/128, 1);
    gemm_kernel<1><<<g3, 256>>>(nullptr, Wo, bo, nullptr, nullptr, nullptr, nullptr, hs);

    // 5) layernorm -> d_out
    ln_kernel<<<Mtot, 256>>>(lng, lnb, out);
}

// round 13
// speedup vs baseline: 2.2583x; 1.2395x over previous
#include <cuda_runtime.h>
#include <cuda_bf16.h>
#include <math.h>
#include <stdint.h>

// Problem constants
#define Bc   2
#define Lc   2048
#define Dc   1024
#define Hc   16
#define HDc  64
#define Mtot (Bc*Lc)      // 4096
#define BHL  (Bc*Hc*Lc)   // 65536

// ---- scratch (device globals: allocation-free, graph-capturable) ----
__device__ float  g_q[(size_t)BHL*HDc];      // fp32 QKV-gemm out (pre-rotary)
__device__ float  g_k[(size_t)BHL*HDc];
__device__ float  g_x[(size_t)Mtot*Dc];      // pre-LN
__device__ float2 g_cs[BHL];                 // (cos phi, sin phi)
// packed bf16 tensors (16B aligned via uint4)
__device__ uint4  g_hsh[(size_t)Mtot*Dc/8];  // hidden_states bf16
__device__ uint4  g_wqh[(size_t)Dc*Dc/8];    // weights bf16
__device__ uint4  g_wkh[(size_t)Dc*Dc/8];
__device__ uint4  g_wvh[(size_t)Dc*Dc/8];
__device__ uint4  g_woh[(size_t)Dc*Dc/8];
__device__ uint4  g_qh[(size_t)BHL*HDc/8];   // [bh][l][hd/2 u32] (q*0.125, rotated)
__device__ uint4  g_kh[(size_t)BHL*HDc/8];   // [bh][l][hd/2 u32]
__device__ uint4  g_vth[(size_t)BHL*HDc/8];  // [bh][d][Lc/2 u32] (V transposed)
__device__ uint4  g_ctxh[(size_t)Mtot*Dc/8]; // [B,L,D/2 u32]

// ---- helpers ----
__device__ __forceinline__ uint32_t pkbf2(float lo, float hi) {
    __nv_bfloat162 h = __float22bfloat162_rn(make_float2(lo, hi));
    return *(uint32_t*)&h;
}
__device__ __forceinline__ void mma_bf16(float* c, const uint32_t* a,
                                         uint32_t b0, uint32_t b1)
{
    asm volatile(
        "mma.sync.aligned.m16n8k16.row.col.f32.bf16.bf16.f32 "
        "{%0,%1,%2,%3}, {%4,%5,%6,%7}, {%8,%9}, {%0,%1,%2,%3};"
        : "+f"(c[0]), "+f"(c[1]), "+f"(c[2]), "+f"(c[3])
        : "r"(a[0]), "r"(a[1]), "r"(a[2]), "r"(a[3]), "r"(b0), "r"(b1));
}
__device__ __forceinline__ uint32_t smem_u32(const void* p) {
    return (uint32_t)__cvta_generic_to_shared(p);
}
__device__ __forceinline__ void ldsm_x4(uint32_t* r, uint32_t addr) {
    asm volatile("ldmatrix.sync.aligned.m8n8.x4.shared.b16 {%0,%1,%2,%3}, [%4];"
                 : "=r"(r[0]), "=r"(r[1]), "=r"(r[2]), "=r"(r[3]) : "r"(addr));
}
__device__ __forceinline__ void cpa16(uint32_t dst, const void* src) {
    asm volatile("cp.async.ca.shared.global [%0], [%1], 16;\n" :: "r"(dst), "l"(src));
}

// ============================================================
// fp32 -> packed bf16 conversion (hs + 4 weight matrices).
// blockIdx.y selects tensor. Bit-identical rounding to the old
// in-GEMM pkbf2 staging (so GEMM results are unchanged).
// ============================================================
__global__ __launch_bounds__(256)
void conv_kernel(const float* __restrict__ hs,
                 const float* __restrict__ Wq, const float* __restrict__ Wk,
                 const float* __restrict__ Wv, const float* __restrict__ Wo)
{
    const int y = blockIdx.y;
    const float* src; uint32_t* dst; int n4;
    if (y == 0)      { src = hs; dst = (uint32_t*)g_hsh; n4 = Mtot*Dc/4; }
    else if (y == 1) { src = Wq; dst = (uint32_t*)g_wqh; n4 = Dc*Dc/4; }
    else if (y == 2) { src = Wk; dst = (uint32_t*)g_wkh; n4 = Dc*Dc/4; }
    else if (y == 3) { src = Wv; dst = (uint32_t*)g_wvh; n4 = Dc*Dc/4; }
    else             { src = Wo; dst = (uint32_t*)g_woh; n4 = Dc*Dc/4; }
    const int idx = blockIdx.x * blockDim.x + threadIdx.x;
    if (idx >= n4) return;
    float4 v = ((const float4*)src)[idx];
    ((uint2*)dst)[idx] = make_uint2(pkbf2(v.x, v.y), pkbf2(v.z, v.w));
}

// ============================================================
// bf16 tile GEMM: all operands pre-packed bf16 in global,
// cp.async double-buffered staging, ldmatrix fragments.
// MODE 0: A=g_hsh; z selects Wq/Wk/Wv; z<2 -> fp32 g_q/g_k;
//         z==2 -> bf16 g_vth transposed [bh][d][l].
// MODE 1: A=g_ctxh, W=g_woh; out = g_x = ctx@Wo^T + bo + residual.
// 128x128 tile, K-chunk 32, 256 thr = 8 warps (2m x 4n).
// ============================================================
template<int MODE>
__global__ __launch_bounds__(256)
void gemm_kernel(const float* __restrict__ bias0,
                 const float* __restrict__ bias1,
                 const float* __restrict__ bias2,
                 const float* __restrict__ residual)
{
    const uint32_t* Asrc; const uint32_t* Wsrc; const float* bias;
    const int z = (MODE == 0) ? blockIdx.z : 0;
    if (MODE == 0) {
        Asrc = (const uint32_t*)g_hsh;
        Wsrc = (z == 0) ? (const uint32_t*)g_wqh
             : (z == 1) ? (const uint32_t*)g_wkh : (const uint32_t*)g_wvh;
        bias = (z == 0) ? bias0 : (z == 1) ? bias1 : bias2;
    } else {
        Asrc = (const uint32_t*)g_ctxh;
        Wsrc = (const uint32_t*)g_woh;
        bias = bias0;
    }

    __shared__ uint32_t Au[2][128][20];
    __shared__ uint32_t Wu[2][128][20];

    const int tid  = threadIdx.x;
    const int lane = tid & 31;
    const int wid  = tid >> 5;
    const int g    = lane >> 2, tg = lane & 3;
    const int warpM = wid & 1, warpN = wid >> 1;
    const int m0 = blockIdx.y * 128;
    const int n0 = blockIdx.x * 128;

    const int a_lr = lane & 15;
    const int a_lc = (lane >> 4) << 2;
    const int b_lr = ((lane >> 4) << 3) + (lane & 7);
    const int b_lc = ((lane >> 3) & 1) << 2;

    const uint32_t* Abase = Asrc + (size_t)m0 * (Dc/2);
    const uint32_t* Wbase = Wsrc + (size_t)n0 * (Dc/2);

    // stage one 128x32 bf16 chunk of A and W: 512 16B chunks each, 2/thread/matrix
#define G_STAGE(k0_, buf_) do {                                                \
        _Pragma("unroll")                                                      \
        for (int i_ = 0; i_ < 2; i_++) {                                       \
            const int c_ = tid + i_ * 256;                                     \
            const int r_ = c_ >> 2, c4_ = (c_ & 3) * 4;                        \
            cpa16(smem_u32(&Au[buf_][r_][c4_]),                                \
                  Abase + (size_t)r_ * (Dc/2) + ((k0_) >> 1) + c4_);           \
            cpa16(smem_u32(&Wu[buf_][r_][c4_]),                                \
                  Wbase + (size_t)r_ * (Dc/2) + ((k0_) >> 1) + c4_);           \
        }                                                                      \
        asm volatile("cp.async.commit_group;\n" ::);                           \
    } while (0)

    float acc[4][4][4];
    #pragma unroll
    for (int mt = 0; mt < 4; mt++)
        #pragma unroll
        for (int nt = 0; nt < 4; nt++)
            #pragma unroll
            for (int i = 0; i < 4; i++) acc[mt][nt][i] = 0.f;

    G_STAGE(0, 0);
    asm volatile("cp.async.wait_group 0;\n" ::);
    __syncthreads();

    int cur = 0;
    for (int k0 = 0; k0 < Dc; k0 += 32) {
        const bool more = (k0 + 32 < Dc);
        if (more) G_STAGE(k0 + 32, cur ^ 1);

        #pragma unroll
        for (int ks = 0; ks < 2; ks++) {
            uint32_t af[4][4], bfr[2][4];
            #pragma unroll
            for (int mt = 0; mt < 4; mt++)
                ldsm_x4(af[mt], smem_u32(&Au[cur][warpM*64 + mt*16 + a_lr][ks*8 + a_lc]));
            #pragma unroll
            for (int ntp = 0; ntp < 2; ntp++)
                ldsm_x4(bfr[ntp], smem_u32(&Wu[cur][warpN*32 + ntp*16 + b_lr][ks*8 + b_lc]));
            #pragma unroll
            for (int mt = 0; mt < 4; mt++)
                #pragma unroll
                for (int nt = 0; nt < 4; nt++)
                    mma_bf16(acc[mt][nt], af[mt], bfr[nt>>1][(nt&1)*2], bfr[nt>>1][(nt&1)*2+1]);
        }

        if (more) asm volatile("cp.async.wait_group 0;\n" ::);
        __syncthreads();
        cur ^= 1;
    }
#undef G_STAGE

    // epilogue
    #pragma unroll
    for (int mt = 0; mt < 4; mt++) {
        const int mA = m0 + warpM * 64 + mt * 16 + g;
        #pragma unroll
        for (int nt = 0; nt < 4; nt++) {
            const int n = n0 + warpN * 32 + nt * 8 + 2 * tg;
            const float b0v = bias[n], b1v = bias[n + 1];
            #pragma unroll
            for (int rh = 0; rh < 2; rh++) {
                const int m = mA + rh * 8;
                float v0 = acc[mt][nt][rh * 2]     + b0v;
                float v1 = acc[mt][nt][rh * 2 + 1] + b1v;
                if (MODE == 0) {
                    const int bb = m >> 11;
                    const int l  = m & (Lc - 1);
                    const int h  = n >> 6;
                    const int d  = n & 63;
                    if (z == 2) {
                        __nv_bfloat16* vb = (__nv_bfloat16*)g_vth +
                            (((size_t)bb*Hc + h)*HDc + d)*Lc + l;
                        vb[0]  = __float2bfloat16_rn(v0);
                        vb[Lc] = __float2bfloat16_rn(v1);
                    } else {
                        float* out = (z == 0) ? g_q : g_k;
                        *(float2*)&out[(((size_t)bb*Hc + h)*Lc + l)*HDc + d] =
                            make_float2(v0, v1);
                    }
                } else {
                    const float2 rr = *(const float2*)&residual[(size_t)m*Dc + n];
                    *(float2*)&g_x[(size_t)m*Dc + n] = make_float2(v0 + rr.x, v1 + rr.y);
                }
            }
        }
    }
}

// ============================================================
// Rotary: fp32 in (g_q/g_k), packed-bf16 out (g_qh/g_kh) + cos/sin table.
// q pre-scaled by 0.125 (exact pow2). phi layout [B,L,H].
// ============================================================
__global__ __launch_bounds__(256)
void rotary_kernel(const float* __restrict__ phi)
{
    const int rest = blockIdx.x * blockDim.x + threadIdx.x;  // (b*H+h)*L + l
    if (rest >= BHL) return;
    const int l  = rest & (Lc - 1);
    const int bh = rest >> 11;
    const int h  = bh & (Hc - 1);
    const int b  = bh >> 4;

    const float p = phi[((size_t)b*Lc + l)*Hc + h];
    const float c = cosf(p);
    const float s = sinf(p);
    g_cs[rest] = make_float2(c, s);

    {
        const float4* qp = (const float4*)(g_q + (size_t)rest * HDc);
        float x[64];
        #pragma unroll
        for (int i = 0; i < 16; i++) *(float4*)&x[i*4] = qp[i];
        float r[64];
        #pragma unroll
        for (int d = 0; d < 32; d++) {
            r[d]      = (x[d] * c - x[d + 32] * s) * 0.125f;
            r[d + 32] = (x[d + 32] * c + x[d] * s) * 0.125f;
        }
        uint32_t* qd = (uint32_t*)g_qh + (size_t)rest * 32;
        #pragma unroll
        for (int i = 0; i < 32; i++) qd[i] = pkbf2(r[2*i], r[2*i + 1]);
    }
    {
        const float4* kp = (const float4*)(g_k + (size_t)rest * HDc);
        float x[64];
        #pragma unroll
        for (int i = 0; i < 16; i++) *(float4*)&x[i*4] = kp[i];
        float r[64];
        #pragma unroll
        for (int d = 0; d < 32; d++) {
            r[d]      = x[d] * c - x[d + 32] * s;
            r[d + 32] = x[d + 32] * c + x[d] * s;
        }
        uint32_t* kd = (uint32_t*)g_kh + (size_t)rest * 32;
        #pragma unroll
        for (int i = 0; i < 32; i++) kd[i] = pkbf2(r[2*i], r[2*i + 1]);
    }
}

// ============================================================
// bf16 tensor-core flash attention: cp.async double-buffered K/V,
// ldmatrix fragments, fp32 softmax/mask. grid (Lc/64, Hc, Bc), 128 thr.
// ============================================================
__global__ __launch_bounds__(128)
void attn_kernel(const float* __restrict__ amask)
{
    __shared__ uint32_t Ps[64][36];      // Q tile, then P tiles (per-warp rows)
    __shared__ uint32_t Ku[2][64][36];
    __shared__ uint32_t Vu[2][64][36];
    __shared__ float2 csk[2][64];
    __shared__ float  am[2][64];

    const int tid  = threadIdx.x;
    const int lane = tid & 31;
    const int warp = tid >> 5;
    const int g    = lane >> 2, tg = lane & 3;

    const int a_lr = lane & 15;
    const int a_lc = (lane >> 4) << 2;
    const int b_lr = ((lane >> 4) << 3) + (lane & 7);
    const int b_lc = ((lane >> 3) & 1) << 2;

    const int b  = blockIdx.z;
    const int h  = blockIdx.y;
    const int q0 = blockIdx.x * 64;
    const int bh = b * Hc + h;
    const size_t bhL = (size_t)bh * Lc;

    const uint32_t* qb = (const uint32_t*)g_qh  + bhL * 32;
    const uint32_t* kb = (const uint32_t*)g_kh  + bhL * 32;
    const uint32_t* vb = (const uint32_t*)g_vth + (size_t)bh * HDc * (Lc/2);

    const int row  = tid >> 1;
    const int half = tid & 1;

    // --- stage Q tile (already bf16) ---
    {
        const uint32_t* src = qb + (size_t)(q0 + row) * 32 + half * 16;
        *(uint4*)&Ps[row][half * 16]      = *(const uint4*)(src);
        *(uint4*)&Ps[row][half * 16 + 4]  = *(const uint4*)(src + 4);
        *(uint4*)&Ps[row][half * 16 + 8]  = *(const uint4*)(src + 8);
        *(uint4*)&Ps[row][half * 16 + 12] = *(const uint4*)(src + 12);
    }
    __syncwarp();

    uint32_t qa[4][4];
    #pragma unroll
    for (int ks = 0; ks < 4; ks++)
        ldsm_x4(qa[ks], smem_u32(&Ps[warp*16 + a_lr][ks*8 + a_lc]));

    const int qrow = warp * 16 + g;
    const float2 csq0 = g_cs[bhL + q0 + qrow];
    const float2 csq1 = g_cs[bhL + q0 + qrow + 8];
    const int qg0 = q0 + qrow, qg1 = q0 + qrow + 8;
    __syncwarp();

#define STAGE_KV(kt_, buf_) do {                                              \
        _Pragma("unroll")                                                     \
        for (int i_ = 0; i_ < 4; i_++) {                                      \
            const int c_ = tid + i_ * 128;                                    \
            const int r_ = c_ >> 3, c4_ = (c_ & 7) * 4;                       \
            cpa16(smem_u32(&Ku[buf_][r_][c4_]),                               \
                  kb + (size_t)((kt_) + r_) * 32 + c4_);                      \
            cpa16(smem_u32(&Vu[buf_][r_][c4_]),                               \
                  vb + (size_t)r_ * (Lc/2) + ((kt_) >> 1) + c4_);             \
        }                                                                     \
        asm volatile("cp.async.commit_group;\n" ::);                          \
    } while (0)
#define STAGE_CSAM(kt_, buf_) do {                                            \
        if (tid < 64) {                                                       \
            csk[buf_][tid] = g_cs[bhL + (kt_) + tid];                         \
            am[buf_][tid]  = amask[(size_t)b * Lc + (kt_) + tid];             \
        }                                                                     \
    } while (0)

    STAGE_KV(0, 0);
    STAGE_CSAM(0, 0);
    asm volatile("cp.async.wait_group 0;\n" ::);
    __syncthreads();

    float m0r = -3.4e38f, m1r = -3.4e38f;
    float l0r = 0.f, l1r = 0.f;
    float oacc[8][4];
    #pragma unroll
    for (int nt = 0; nt < 8; nt++)
        #pragma unroll
        for (int i = 0; i < 4; i++) oacc[nt][i] = 0.f;

    int cur = 0;
    for (int kt = 0; kt < Lc; kt += 64) {
        const bool more = (kt + 64 < Lc);
        if (more) {
            STAGE_KV(kt + 64, cur ^ 1);
            STAGE_CSAM(kt + 64, cur ^ 1);
        }

        // --- scores ---
        float sacc[8][4];
        #pragma unroll
        for (int nt = 0; nt < 8; nt++)
            #pragma unroll
            for (int i = 0; i < 4; i++) sacc[nt][i] = 0.f;
        #pragma unroll
        for (int ks = 0; ks < 4; ks++) {
            #pragma unroll
            for (int ntp = 0; ntp < 4; ntp++) {
                uint32_t kb4[4];
                ldsm_x4(kb4, smem_u32(&Ku[cur][ntp*16 + b_lr][ks*8 + b_lc]));
                mma_bf16(sacc[2*ntp],     qa[ks], kb4[0], kb4[1]);
                mma_bf16(sacc[2*ntp + 1], qa[ks], kb4[2], kb4[3]);
            }
        }

        // --- mask + online softmax (fp32) ---
        float cmax0 = -3.4e38f, cmax1 = -3.4e38f;
        #pragma unroll
        for (int nt = 0; nt < 8; nt++) {
            const int c0 = nt * 8 + 2 * tg;
            const float2 ck0 = csk[cur][c0], ck1 = csk[cur][c0 + 1];
            const float a0 = am[cur][c0], a1 = am[cur][c0 + 1];
            const int kg0 = kt + c0, kg1 = kt + c0 + 1;

            float dc;
            dc = fmaf(csq0.x, ck0.x, csq0.y * ck0.y);
            if (dc < -0.7f && kg0 != qg0) sacc[nt][0] = -1e9f;
            dc = fmaf(csq0.x, ck1.x, csq0.y * ck1.y);
            if (dc < -0.7f && kg1 != qg0) sacc[nt][1] = -1e9f;
            dc = fmaf(csq1.x, ck0.x, csq1.y * ck0.y);
            if (dc < -0.7f && kg0 != qg1) sacc[nt][2] = -1e9f;
            dc = fmaf(csq1.x, ck1.x, csq1.y * ck1.y);
            if (dc < -0.7f && kg1 != qg1) sacc[nt][3] = -1e9f;

            sacc[nt][0] += a0; sacc[nt][1] += a1;
            sacc[nt][2] += a0; sacc[nt][3] += a1;
            cmax0 = fmaxf(cmax0, fmaxf(sacc[nt][0], sacc[nt][1]));
            cmax1 = fmaxf(cmax1, fmaxf(sacc[nt][2], sacc[nt][3]));
        }
        cmax0 = fmaxf(cmax0, __shfl_xor_sync(0xffffffffu, cmax0, 1));
        cmax0 = fmaxf(cmax0, __shfl_xor_sync(0xffffffffu, cmax0, 2));
        cmax1 = fmaxf(cmax1, __shfl_xor_sync(0xffffffffu, cmax1, 1));
        cmax1 = fmaxf(cmax1, __shfl_xor_sync(0xffffffffu, cmax1, 2));

        if (cmax0 > m0r) {
            const float corr = __expf(m0r - cmax0);
            m0r = cmax0; l0r *= corr;
            #pragma unroll
            for (int nt = 0; nt < 8; nt++) { oacc[nt][0] *= corr; oacc[nt][1] *= corr; }
        }
        if (cmax1 > m1r) {
            const float corr = __expf(m1r - cmax1);
            m1r = cmax1; l1r *= corr;
            #pragma unroll
            for (int nt = 0; nt < 8; nt++) { oacc[nt][2] *= corr; oacc[nt][3] *= corr; }
        }

        #pragma unroll
        for (int nt = 0; nt < 8; nt++) {
            float p00 = __expf(sacc[nt][0] - m0r);
            float p01 = __expf(sacc[nt][1] - m0r);
            float p10 = __expf(sacc[nt][2] - m1r);
            float p11 = __expf(sacc[nt][3] - m1r);
            l0r += p00 + p01;
            l1r += p10 + p11;
            Ps[qrow    ][nt * 4 + tg] = pkbf2(p00, p01);
            Ps[qrow + 8][nt * 4 + tg] = pkbf2(p10, p11);
        }
        __syncwarp();

        // --- PV ---
        #pragma unroll
        for (int ks = 0; ks < 4; ks++) {
            uint32_t pa[4];
            ldsm_x4(pa, smem_u32(&Ps[warp*16 + a_lr][ks*8 + a_lc]));
            #pragma unroll
            for (int ntp = 0; ntp < 4; ntp++) {
                uint32_t vb4[4];
                ldsm_x4(vb4, smem_u32(&Vu[cur][ntp*16 + b_lr][ks*8 + b_lc]));
                mma_bf16(oacc[2*ntp],     pa, vb4[0], vb4[1]);
                mma_bf16(oacc[2*ntp + 1], pa, vb4[2], vb4[3]);
            }
        }

        if (more) asm volatile("cp.async.wait_group 0;\n" ::);
        __syncthreads();
        cur ^= 1;
    }

    // --- finalize: write ctx as packed bf16 ---
    l0r += __shfl_xor_sync(0xffffffffu, l0r, 1);
    l0r += __shfl_xor_sync(0xffffffffu, l0r, 2);
    l1r += __shfl_xor_sync(0xffffffffu, l1r, 1);
    l1r += __shfl_xor_sync(0xffffffffu, l1r, 2);
    const float inv0 = 1.f / l0r;
    const float inv1 = 1.f / l1r;

    uint32_t* ctxu = (uint32_t*)g_ctxh;
    const size_t base0 = ((size_t)(b * Lc + qg0) * Dc + h * HDc) >> 1;
    const size_t base1 = ((size_t)(b * Lc + qg1) * Dc + h * HDc) >> 1;
    #pragma unroll
    for (int nt = 0; nt < 8; nt++) {
        const int d = nt * 8 + 2 * tg;
        ctxu[base0 + (d >> 1)] = pkbf2(oacc[nt][0] * inv0, oacc[nt][1] * inv0);
        ctxu[base1 + (d >> 1)] = pkbf2(oacc[nt][2] * inv1, oacc[nt][3] * inv1);
    }
#undef STAGE_KV
#undef STAGE_CSAM
}

// ============================================================
// LayerNorm over last dim (1024). one block per row, 256 threads.
// ============================================================
__global__ __launch_bounds__(256)
void ln_kernel(const float* __restrict__ gamma, const float* __restrict__ beta,
               float* __restrict__ out)
{
    const int row = blockIdx.x;
    const int tid = threadIdx.x;
    const float4 v = ((const float4*)(g_x + (size_t)row * Dc))[tid];
    float s  = v.x + v.y + v.z + v.w;
    float sq = v.x*v.x + v.y*v.y + v.z*v.z + v.w*v.w;
    #pragma unroll
    for (int off = 16; off > 0; off >>= 1) {
        s  += __shfl_xor_sync(0xffffffffu, s,  off);
        sq += __shfl_xor_sync(0xffffffffu, sq, off);
    }
    __shared__ float ssum[8], ssq[8];
    const int w = tid >> 5;
    if ((tid & 31) == 0) { ssum[w] = s; ssq[w] = sq; }
    __syncthreads();
    if (tid == 0) {
        float ts = 0.f, tq = 0.f;
        #pragma unroll
        for (int i = 0; i < 8; i++) { ts += ssum[i]; tq += ssq[i]; }
        ssum[0] = ts; ssq[0] = tq;
    }
    __syncthreads();
    const float mean = ssum[0] * (1.f / Dc);
    const float var  = ssq[0]  * (1.f / Dc) - mean * mean;
    const float inv  = rsqrtf(var + 1e-12f);
    const float4 gv = ((const float4*)gamma)[tid];
    const float4 bv = ((const float4*)beta)[tid];
    float4 ov;
    ov.x = (v.x - mean) * inv * gv.x + bv.x;
    ov.y = (v.y - mean) * inv * gv.y + bv.y;
    ov.z = (v.z - mean) * inv * gv.z + bv.z;
    ov.w = (v.w - mean) * inv * gv.w + bv.w;
    ((float4*)out)[(size_t)row * (Dc/4) + tid] = ov;
}

// ============================================================
// launch
// ============================================================
extern "C" void kernel_launch(void* const* d_in, const int* in_sizes, int n_in,
                              void* d_out, int out_size)
{
    const float* hs    = (const float*)d_in[0];
    const float* amask = (const float*)d_in[1];
    const float* phi   = (const float*)d_in[2];
    const float* Wq    = (const float*)d_in[3];
    const float* bq    = (const float*)d_in[4];
    const float* Wk    = (const float*)d_in[5];
    const float* bk    = (const float*)d_in[6];
    const float* Wv    = (const float*)d_in[7];
    const float* bv    = (const float*)d_in[8];
    const float* Wo    = (const float*)d_in[9];
    const float* bo    = (const float*)d_in[10];
    const float* lng   = (const float*)d_in[11];
    const float* lnb   = (const float*)d_in[12];
    float* out = (float*)d_out;

    // 0) pack hs + weights to bf16 (hs is the largest: Mtot*Dc/4 vec4 elems)
    dim3 gc((Mtot*Dc/4 + 255)/256, 5);
    conv_kernel<<<gc, 256>>>(hs, Wq, Wk, Wv, Wo);

    // 1) QKV projections -> g_q/g_k fp32, g_vth bf16 (transposed)
    dim3 g0(Dc/128, Mtot/128, 3);
    gemm_kernel<0><<<g0, 256>>>(bq, bk, bv, nullptr);

    // 2) rotary -> g_qh/g_kh packed bf16 + cos/sin table
    rotary_kernel<<<BHL/256, 256>>>(phi);

    // 3) attention -> g_ctxh packed bf16
    dim3 g2(Lc/64, Hc, Bc);
    attn_kernel<<<g2, 128>>>(amask);

    // 4) output projection + residual -> g_x
    dim3 g3(Dc/128, Mtot/128, 1);
    gemm_kernel<1><<<g3, 256>>>(bo, nullptr, nullptr, hs);

    // 5) layernorm -> d_out
    ln_kernel<<<Mtot, 256>>>(lng, lnb, out);
}

// round 14
// speedup vs baseline: 2.3529x; 1.0419x over previous
#include <cuda_runtime.h>
#include <cuda_bf16.h>
#include <math.h>
#include <stdint.h>

// Problem constants
#define Bc   2
#define Lc   2048
#define Dc   1024
#define Hc   16
#define HDc  64
#define Mtot (Bc*Lc)      // 4096
#define BHL  (Bc*Hc*Lc)   // 65536

// ---- scratch (device globals: allocation-free, graph-capturable) ----
__device__ float  g_q[(size_t)BHL*HDc];      // fp32 QKV-gemm out (pre-rotary)
__device__ float  g_k[(size_t)BHL*HDc];
__device__ float  g_x[(size_t)Mtot*Dc];      // pre-LN
__device__ float2 g_cs[BHL];                 // (cos phi, sin phi)
// packed bf16 tensors (16B aligned via uint4)
__device__ uint4  g_hsh[(size_t)Mtot*Dc/8];  // hidden_states bf16
__device__ uint4  g_wqh[(size_t)Dc*Dc/8];    // weights bf16
__device__ uint4  g_wkh[(size_t)Dc*Dc/8];
__device__ uint4  g_wvh[(size_t)Dc*Dc/8];
__device__ uint4  g_woh[(size_t)Dc*Dc/8];
__device__ uint4  g_qh[(size_t)BHL*HDc/8];   // [bh][l][hd/2 u32] (q*0.125, rotated)
__device__ uint4  g_kh[(size_t)BHL*HDc/8];   // [bh][l][hd/2 u32]
__device__ uint4  g_vth[(size_t)BHL*HDc/8];  // [bh][d][Lc/2 u32] (V transposed)
__device__ uint4  g_ctxh[(size_t)Mtot*Dc/8]; // [B,L,D/2 u32]

// ---- helpers ----
__device__ __forceinline__ uint32_t pkbf2(float lo, float hi) {
    __nv_bfloat162 h = __float22bfloat162_rn(make_float2(lo, hi));
    return *(uint32_t*)&h;
}
__device__ __forceinline__ void mma_bf16(float* c, const uint32_t* a,
                                         uint32_t b0, uint32_t b1)
{
    asm volatile(
        "mma.sync.aligned.m16n8k16.row.col.f32.bf16.bf16.f32 "
        "{%0,%1,%2,%3}, {%4,%5,%6,%7}, {%8,%9}, {%0,%1,%2,%3};"
        : "+f"(c[0]), "+f"(c[1]), "+f"(c[2]), "+f"(c[3])
        : "r"(a[0]), "r"(a[1]), "r"(a[2]), "r"(a[3]), "r"(b0), "r"(b1));
}
__device__ __forceinline__ uint32_t smem_u32(const void* p) {
    return (uint32_t)__cvta_generic_to_shared(p);
}
__device__ __forceinline__ void ldsm_x4(uint32_t* r, uint32_t addr) {
    asm volatile("ldmatrix.sync.aligned.m8n8.x4.shared.b16 {%0,%1,%2,%3}, [%4];"
                 : "=r"(r[0]), "=r"(r[1]), "=r"(r[2]), "=r"(r[3]) : "r"(addr));
}
__device__ __forceinline__ void cpa16(uint32_t dst, const void* src) {
    asm volatile("cp.async.ca.shared.global [%0], [%1], 16;\n" :: "r"(dst), "l"(src));
}

// ============================================================
// fp32 -> packed bf16 conversion (hs + 4 weight matrices).
// ============================================================
__global__ __launch_bounds__(256)
void conv_kernel(const float* __restrict__ hs,
                 const float* __restrict__ Wq, const float* __restrict__ Wk,
                 const float* __restrict__ Wv, const float* __restrict__ Wo)
{
    const int y = blockIdx.y;
    const float* src; uint32_t* dst; int n4;
    if (y == 0)      { src = hs; dst = (uint32_t*)g_hsh; n4 = Mtot*Dc/4; }
    else if (y == 1) { src = Wq; dst = (uint32_t*)g_wqh; n4 = Dc*Dc/4; }
    else if (y == 2) { src = Wk; dst = (uint32_t*)g_wkh; n4 = Dc*Dc/4; }
    else if (y == 3) { src = Wv; dst = (uint32_t*)g_wvh; n4 = Dc*Dc/4; }
    else             { src = Wo; dst = (uint32_t*)g_woh; n4 = Dc*Dc/4; }
    const int idx = blockIdx.x * blockDim.x + threadIdx.x;
    if (idx >= n4) return;
    float4 v = ((const float4*)src)[idx];
    ((uint2*)dst)[idx] = make_uint2(pkbf2(v.x, v.y), pkbf2(v.z, v.w));
}

// ============================================================
// bf16 tile GEMM: pre-packed bf16 operands, cp.async double-buffer,
// ldmatrix fragments. (unchanged from round 13)
// ============================================================
template<int MODE>
__global__ __launch_bounds__(256)
void gemm_kernel(const float* __restrict__ bias0,
                 const float* __restrict__ bias1,
                 const float* __restrict__ bias2,
                 const float* __restrict__ residual)
{
    const uint32_t* Asrc; const uint32_t* Wsrc; const float* bias;
    const int z = (MODE == 0) ? blockIdx.z : 0;
    if (MODE == 0) {
        Asrc = (const uint32_t*)g_hsh;
        Wsrc = (z == 0) ? (const uint32_t*)g_wqh
             : (z == 1) ? (const uint32_t*)g_wkh : (const uint32_t*)g_wvh;
        bias = (z == 0) ? bias0 : (z == 1) ? bias1 : bias2;
    } else {
        Asrc = (const uint32_t*)g_ctxh;
        Wsrc = (const uint32_t*)g_woh;
        bias = bias0;
    }

    __shared__ uint32_t Au[2][128][20];
    __shared__ uint32_t Wu[2][128][20];

    const int tid  = threadIdx.x;
    const int lane = tid & 31;
    const int wid  = tid >> 5;
    const int g    = lane >> 2, tg = lane & 3;
    const int warpM = wid & 1, warpN = wid >> 1;
    const int m0 = blockIdx.y * 128;
    const int n0 = blockIdx.x * 128;

    const int a_lr = lane & 15;
    const int a_lc = (lane >> 4) << 2;
    const int b_lr = ((lane >> 4) << 3) + (lane & 7);
    const int b_lc = ((lane >> 3) & 1) << 2;

    const uint32_t* Abase = Asrc + (size_t)m0 * (Dc/2);
    const uint32_t* Wbase = Wsrc + (size_t)n0 * (Dc/2);

#define G_STAGE(k0_, buf_) do {                                                \
        _Pragma("unroll")                                                      \
        for (int i_ = 0; i_ < 2; i_++) {                                       \
            const int c_ = tid + i_ * 256;                                     \
            const int r_ = c_ >> 2, c4_ = (c_ & 3) * 4;                        \
            cpa16(smem_u32(&Au[buf_][r_][c4_]),                                \
                  Abase + (size_t)r_ * (Dc/2) + ((k0_) >> 1) + c4_);           \
            cpa16(smem_u32(&Wu[buf_][r_][c4_]),                                \
                  Wbase + (size_t)r_ * (Dc/2) + ((k0_) >> 1) + c4_);           \
        }                                                                      \
        asm volatile("cp.async.commit_group;\n" ::);                           \
    } while (0)

    float acc[4][4][4];
    #pragma unroll
    for (int mt = 0; mt < 4; mt++)
        #pragma unroll
        for (int nt = 0; nt < 4; nt++)
            #pragma unroll
            for (int i = 0; i < 4; i++) acc[mt][nt][i] = 0.f;

    G_STAGE(0, 0);
    asm volatile("cp.async.wait_group 0;\n" ::);
    __syncthreads();

    int cur = 0;
    for (int k0 = 0; k0 < Dc; k0 += 32) {
        const bool more = (k0 + 32 < Dc);
        if (more) G_STAGE(k0 + 32, cur ^ 1);

        #pragma unroll
        for (int ks = 0; ks < 2; ks++) {
            uint32_t af[4][4], bfr[2][4];
            #pragma unroll
            for (int mt = 0; mt < 4; mt++)
                ldsm_x4(af[mt], smem_u32(&Au[cur][warpM*64 + mt*16 + a_lr][ks*8 + a_lc]));
            #pragma unroll
            for (int ntp = 0; ntp < 2; ntp++)
                ldsm_x4(bfr[ntp], smem_u32(&Wu[cur][warpN*32 + ntp*16 + b_lr][ks*8 + b_lc]));
            #pragma unroll
            for (int mt = 0; mt < 4; mt++)
                #pragma unroll
                for (int nt = 0; nt < 4; nt++)
                    mma_bf16(acc[mt][nt], af[mt], bfr[nt>>1][(nt&1)*2], bfr[nt>>1][(nt&1)*2+1]);
        }

        if (more) asm volatile("cp.async.wait_group 0;\n" ::);
        __syncthreads();
        cur ^= 1;
    }
#undef G_STAGE

    // epilogue
    #pragma unroll
    for (int mt = 0; mt < 4; mt++) {
        const int mA = m0 + warpM * 64 + mt * 16 + g;
        #pragma unroll
        for (int nt = 0; nt < 4; nt++) {
            const int n = n0 + warpN * 32 + nt * 8 + 2 * tg;
            const float b0v = bias[n], b1v = bias[n + 1];
            #pragma unroll
            for (int rh = 0; rh < 2; rh++) {
                const int m = mA + rh * 8;
                float v0 = acc[mt][nt][rh * 2]     + b0v;
                float v1 = acc[mt][nt][rh * 2 + 1] + b1v;
                if (MODE == 0) {
                    const int bb = m >> 11;
                    const int l  = m & (Lc - 1);
                    const int h  = n >> 6;
                    const int d  = n & 63;
                    if (z == 2) {
                        __nv_bfloat16* vb = (__nv_bfloat16*)g_vth +
                            (((size_t)bb*Hc + h)*HDc + d)*Lc + l;
                        vb[0]  = __float2bfloat16_rn(v0);
                        vb[Lc] = __float2bfloat16_rn(v1);
                    } else {
                        float* out = (z == 0) ? g_q : g_k;
                        *(float2*)&out[(((size_t)bb*Hc + h)*Lc + l)*HDc + d] =
                            make_float2(v0, v1);
                    }
                } else {
                    const float2 rr = *(const float2*)&residual[(size_t)m*Dc + n];
                    *(float2*)&g_x[(size_t)m*Dc + n] = make_float2(v0 + rr.x, v1 + rr.y);
                }
            }
        }
    }
}

// ============================================================
// Rotary: fp32 in (g_q/g_k), packed-bf16 out + cos/sin table.
// ============================================================
__global__ __launch_bounds__(256)
void rotary_kernel(const float* __restrict__ phi)
{
    const int rest = blockIdx.x * blockDim.x + threadIdx.x;  // (b*H+h)*L + l
    if (rest >= BHL) return;
    const int l  = rest & (Lc - 1);
    const int bh = rest >> 11;
    const int h  = bh & (Hc - 1);
    const int b  = bh >> 4;

    const float p = phi[((size_t)b*Lc + l)*Hc + h];
    const float c = cosf(p);
    const float s = sinf(p);
    g_cs[rest] = make_float2(c, s);

    {
        const float4* qp = (const float4*)(g_q + (size_t)rest * HDc);
        float x[64];
        #pragma unroll
        for (int i = 0; i < 16; i++) *(float4*)&x[i*4] = qp[i];
        float r[64];
        #pragma unroll
        for (int d = 0; d < 32; d++) {
            r[d]      = (x[d] * c - x[d + 32] * s) * 0.125f;
            r[d + 32] = (x[d + 32] * c + x[d] * s) * 0.125f;
        }
        uint32_t* qd = (uint32_t*)g_qh + (size_t)rest * 32;
        #pragma unroll
        for (int i = 0; i < 32; i++) qd[i] = pkbf2(r[2*i], r[2*i + 1]);
    }
    {
        const float4* kp = (const float4*)(g_k + (size_t)rest * HDc);
        float x[64];
        #pragma unroll
        for (int i = 0; i < 16; i++) *(float4*)&x[i*4] = kp[i];
        float r[64];
        #pragma unroll
        for (int d = 0; d < 32; d++) {
            r[d]      = x[d] * c - x[d + 32] * s;
            r[d + 32] = x[d + 32] * c + x[d] * s;
        }
        uint32_t* kd = (uint32_t*)g_kh + (size_t)rest * 32;
        #pragma unroll
        for (int i = 0; i < 32; i++) kd[i] = pkbf2(r[2*i], r[2*i + 1]);
    }
}

// ============================================================
// bf16 tensor-core flash attention, v2:
//  - cp.async double-buffered K/V (as round 13)
//  - fixed-base softmax (no running max: scores are bounded, masked
//    entries underflow to exactly 0; normalization cancels the base)
//  - P stays in registers: QK^T C-fragments re-pack directly into PV
//    A-fragments (no smem round-trip, no ldsm for P)
// grid (Lc/64, Hc, Bc), 128 thr = 4 warps, 16 q-rows per warp.
// ============================================================
__global__ __launch_bounds__(128)
void attn_kernel(const float* __restrict__ amask)
{
    __shared__ uint32_t Qs[64][36];
    __shared__ uint32_t Ku[2][64][36];
    __shared__ uint32_t Vu[2][64][36];
    __shared__ float2 csk[2][64];
    __shared__ float  am[2][64];

    const int tid  = threadIdx.x;
    const int lane = tid & 31;
    const int warp = tid >> 5;
    const int g    = lane >> 2, tg = lane & 3;

    const int a_lr = lane & 15;
    const int a_lc = (lane >> 4) << 2;
    const int b_lr = ((lane >> 4) << 3) + (lane & 7);
    const int b_lc = ((lane >> 3) & 1) << 2;

    const int b  = blockIdx.z;
    const int h  = blockIdx.y;
    const int q0 = blockIdx.x * 64;
    const int bh = b * Hc + h;
    const size_t bhL = (size_t)bh * Lc;

    const uint32_t* qb = (const uint32_t*)g_qh  + bhL * 32;
    const uint32_t* kb = (const uint32_t*)g_kh  + bhL * 32;
    const uint32_t* vb = (const uint32_t*)g_vth + (size_t)bh * HDc * (Lc/2);

    const int row  = tid >> 1;
    const int half = tid & 1;

    // --- stage Q tile (already bf16) ---
    {
        const uint32_t* src = qb + (size_t)(q0 + row) * 32 + half * 16;
        *(uint4*)&Qs[row][half * 16]      = *(const uint4*)(src);
        *(uint4*)&Qs[row][half * 16 + 4]  = *(const uint4*)(src + 4);
        *(uint4*)&Qs[row][half * 16 + 8]  = *(const uint4*)(src + 8);
        *(uint4*)&Qs[row][half * 16 + 12] = *(const uint4*)(src + 12);
    }
    __syncwarp();

    uint32_t qa[4][4];
    #pragma unroll
    for (int ks = 0; ks < 4; ks++)
        ldsm_x4(qa[ks], smem_u32(&Qs[warp*16 + a_lr][ks*8 + a_lc]));

    const int qrow = warp * 16 + g;
    const float2 csq0 = g_cs[bhL + q0 + qrow];
    const float2 csq1 = g_cs[bhL + q0 + qrow + 8];
    const int qg0 = q0 + qrow, qg1 = q0 + qrow + 8;

#define STAGE_KV(kt_, buf_) do {                                              \
        _Pragma("unroll")                                                     \
        for (int i_ = 0; i_ < 4; i_++) {                                      \
            const int c_ = tid + i_ * 128;                                    \
            const int r_ = c_ >> 3, c4_ = (c_ & 7) * 4;                       \
            cpa16(smem_u32(&Ku[buf_][r_][c4_]),                               \
                  kb + (size_t)((kt_) + r_) * 32 + c4_);                      \
            cpa16(smem_u32(&Vu[buf_][r_][c4_]),                               \
                  vb + (size_t)r_ * (Lc/2) + ((kt_) >> 1) + c4_);             \
        }                                                                     \
        asm volatile("cp.async.commit_group;\n" ::);                          \
    } while (0)
#define STAGE_CSAM(kt_, buf_) do {                                            \
        if (tid < 64) {                                                       \
            csk[buf_][tid] = g_cs[bhL + (kt_) + tid];                         \
            am[buf_][tid]  = amask[(size_t)b * Lc + (kt_) + tid];             \
        }                                                                     \
    } while (0)

    STAGE_KV(0, 0);
    STAGE_CSAM(0, 0);
    asm volatile("cp.async.wait_group 0;\n" ::);
    __syncthreads();

    float l0r = 0.f, l1r = 0.f;
    float oacc[8][4];
    #pragma unroll
    for (int nt = 0; nt < 8; nt++)
        #pragma unroll
        for (int i = 0; i < 4; i++) oacc[nt][i] = 0.f;

    int cur = 0;
    for (int kt = 0; kt < Lc; kt += 64) {
        const bool more = (kt + 64 < Lc);
        if (more) {
            STAGE_KV(kt + 64, cur ^ 1);
            STAGE_CSAM(kt + 64, cur ^ 1);
        }

        // --- scores: S[16 x 64] per warp ---
        float sacc[8][4];
        #pragma unroll
        for (int nt = 0; nt < 8; nt++)
            #pragma unroll
            for (int i = 0; i < 4; i++) sacc[nt][i] = 0.f;
        #pragma unroll
        for (int ks = 0; ks < 4; ks++) {
            #pragma unroll
            for (int ntp = 0; ntp < 4; ntp++) {
                uint32_t kb4[4];
                ldsm_x4(kb4, smem_u32(&Ku[cur][ntp*16 + b_lr][ks*8 + b_lc]));
                mma_bf16(sacc[2*ntp],     qa[ks], kb4[0], kb4[1]);
                mma_bf16(sacc[2*ntp + 1], qa[ks], kb4[2], kb4[3]);
            }
        }

        // --- mask + fixed-base exp (fp32, P stays in registers) ---
        #pragma unroll
        for (int nt = 0; nt < 8; nt++) {
            const int c0 = nt * 8 + 2 * tg;
            const float2 ck0 = csk[cur][c0], ck1 = csk[cur][c0 + 1];
            const float a0 = am[cur][c0], a1 = am[cur][c0 + 1];
            const int kg0 = kt + c0, kg1 = kt + c0 + 1;

            float dc;
            dc = fmaf(csq0.x, ck0.x, csq0.y * ck0.y);
            if (dc < -0.7f && kg0 != qg0) sacc[nt][0] = -1e9f;
            dc = fmaf(csq0.x, ck1.x, csq0.y * ck1.y);
            if (dc < -0.7f && kg1 != qg0) sacc[nt][1] = -1e9f;
            dc = fmaf(csq1.x, ck0.x, csq1.y * ck0.y);
            if (dc < -0.7f && kg0 != qg1) sacc[nt][2] = -1e9f;
            dc = fmaf(csq1.x, ck1.x, csq1.y * ck1.y);
            if (dc < -0.7f && kg1 != qg1) sacc[nt][3] = -1e9f;

            const float p0 = __expf(sacc[nt][0] + a0);
            const float p1 = __expf(sacc[nt][1] + a1);
            const float p2 = __expf(sacc[nt][2] + a0);
            const float p3 = __expf(sacc[nt][3] + a1);
            l0r += p0 + p1;
            l1r += p2 + p3;
            sacc[nt][0] = p0; sacc[nt][1] = p1;
            sacc[nt][2] = p2; sacc[nt][3] = p3;
        }

        // --- PV: O += P @ V ; P A-fragments packed straight from sacc ---
        #pragma unroll
        for (int ks = 0; ks < 4; ks++) {
            uint32_t pa[4];
            pa[0] = pkbf2(sacc[2*ks    ][0], sacc[2*ks    ][1]);  // row g,   k 16ks+2tg
            pa[1] = pkbf2(sacc[2*ks    ][2], sacc[2*ks    ][3]);  // row g+8, k 16ks+2tg
            pa[2] = pkbf2(sacc[2*ks + 1][0], sacc[2*ks + 1][1]);  // row g,   k +8
            pa[3] = pkbf2(sacc[2*ks + 1][2], sacc[2*ks + 1][3]);  // row g+8, k +8
            #pragma unroll
            for (int ntp = 0; ntp < 4; ntp++) {
                uint32_t vb4[4];
                ldsm_x4(vb4, smem_u32(&Vu[cur][ntp*16 + b_lr][ks*8 + b_lc]));
                mma_bf16(oacc[2*ntp],     pa, vb4[0], vb4[1]);
                mma_bf16(oacc[2*ntp + 1], pa, vb4[2], vb4[3]);
            }
        }

        if (more) asm volatile("cp.async.wait_group 0;\n" ::);
        __syncthreads();
        cur ^= 1;
    }

    // --- finalize: reduce l over quad, write ctx as packed bf16 ---
    l0r += __shfl_xor_sync(0xffffffffu, l0r, 1);
    l0r += __shfl_xor_sync(0xffffffffu, l0r, 2);
    l1r += __shfl_xor_sync(0xffffffffu, l1r, 1);
    l1r += __shfl_xor_sync(0xffffffffu, l1r, 2);
    const float inv0 = 1.f / l0r;
    const float inv1 = 1.f / l1r;

    uint32_t* ctxu = (uint32_t*)g_ctxh;
    const size_t base0 = ((size_t)(b * Lc + qg0) * Dc + h * HDc) >> 1;
    const size_t base1 = ((size_t)(b * Lc + qg1) * Dc + h * HDc) >> 1;
    #pragma unroll
    for (int nt = 0; nt < 8; nt++) {
        const int d = nt * 8 + 2 * tg;
        ctxu[base0 + (d >> 1)] = pkbf2(oacc[nt][0] * inv0, oacc[nt][1] * inv0);
        ctxu[base1 + (d >> 1)] = pkbf2(oacc[nt][2] * inv1, oacc[nt][3] * inv1);
    }
#undef STAGE_KV
#undef STAGE_CSAM
}

// ============================================================
// LayerNorm over last dim (1024). one block per row, 256 threads.
// ============================================================
__global__ __launch_bounds__(256)
void ln_kernel(const float* __restrict__ gamma, const float* __restrict__ beta,
               float* __restrict__ out)
{
    const int row = blockIdx.x;
    const int tid = threadIdx.x;
    const float4 v = ((const float4*)(g_x + (size_t)row * Dc))[tid];
    float s  = v.x + v.y + v.z + v.w;
    float sq = v.x*v.x + v.y*v.y + v.z*v.z + v.w*v.w;
    #pragma unroll
    for (int off = 16; off > 0; off >>= 1) {
        s  += __shfl_xor_sync(0xffffffffu, s,  off);
        sq += __shfl_xor_sync(0xffffffffu, sq, off);
    }
    __shared__ float ssum[8], ssq[8];
    const int w = tid >> 5;
    if ((tid & 31) == 0) { ssum[w] = s; ssq[w] = sq; }
    __syncthreads();
    if (tid == 0) {
        float ts = 0.f, tq = 0.f;
        #pragma unroll
        for (int i = 0; i < 8; i++) { ts += ssum[i]; tq += ssq[i]; }
        ssum[0] = ts; ssq[0] = tq;
    }
    __syncthreads();
    const float mean = ssum[0] * (1.f / Dc);
    const float var  = ssq[0]  * (1.f / Dc) - mean * mean;
    const float inv  = rsqrtf(var + 1e-12f);
    const float4 gv = ((const float4*)gamma)[tid];
    const float4 bv = ((const float4*)beta)[tid];
    float4 ov;
    ov.x = (v.x - mean) * inv * gv.x + bv.x;
    ov.y = (v.y - mean) * inv * gv.y + bv.y;
    ov.z = (v.z - mean) * inv * gv.z + bv.z;
    ov.w = (v.w - mean) * inv * gv.w + bv.w;
    ((float4*)out)[(size_t)row * (Dc/4) + tid] = ov;
}

// ============================================================
// launch
// ============================================================
extern "C" void kernel_launch(void* const* d_in, const int* in_sizes, int n_in,
                              void* d_out, int out_size)
{
    const float* hs    = (const float*)d_in[0];
    const float* amask = (const float*)d_in[1];
    const float* phi   = (const float*)d_in[2];
    const float* Wq    = (const float*)d_in[3];
    const float* bq    = (const float*)d_in[4];
    const float* Wk    = (const float*)d_in[5];
    const float* bk    = (const float*)d_in[6];
    const float* Wv    = (const float*)d_in[7];
    const float* bv    = (const float*)d_in[8];
    const float* Wo    = (const float*)d_in[9];
    const float* bo    = (const float*)d_in[10];
    const float* lng   = (const float*)d_in[11];
    const float* lnb   = (const float*)d_in[12];
    float* out = (float*)d_out;

    // 0) pack hs + weights to bf16
    dim3 gc((Mtot*Dc/4 + 255)/256, 5);
    conv_kernel<<<gc, 256>>>(hs, Wq, Wk, Wv, Wo);

    // 1) QKV projections -> g_q/g_k fp32, g_vth bf16 (transposed)
    dim3 g0(Dc/128, Mtot/128, 3);
    gemm_kernel<0><<<g0, 256>>>(bq, bk, bv, nullptr);

    // 2) rotary -> g_qh/g_kh packed bf16 + cos/sin table
    rotary_kernel<<<BHL/256, 256>>>(phi);

    // 3) attention -> g_ctxh packed bf16
    dim3 g2(Lc/64, Hc, Bc);
    attn_kernel<<<g2, 128>>>(amask);

    // 4) output projection + residual -> g_x
    dim3 g3(Dc/128, Mtot/128, 1);
    gemm_kernel<1><<<g3, 256>>>(bo, nullptr, nullptr, hs);

    // 5) layernorm -> d_out
    ln_kernel<<<Mtot, 256>>>(lng, lnb, out);
}

// round 15
// speedup vs baseline: 2.5608x; 1.0884x over previous
#include <cuda_runtime.h>
#include <cuda_bf16.h>
#include <math.h>
#include <stdint.h>

// Problem constants
#define Bc   2
#define Lc   2048
#define Dc   1024
#define Hc   16
#define HDc  64
#define Mtot (Bc*Lc)      // 4096
#define BHL  (Bc*Hc*Lc)   // 65536

typedef unsigned long long ull;

// ---- scratch (device globals: allocation-free, graph-capturable) ----
__device__ float  g_q[(size_t)BHL*HDc];      // fp32 QKV-gemm out (pre-rotary)
__device__ float  g_k[(size_t)BHL*HDc];
__device__ float  g_x[(size_t)Mtot*Dc];      // pre-LN
__device__ float2 g_cs[BHL];                 // (cos phi, sin phi)
// packed bf16 tensors (16B aligned via uint4)
__device__ uint4  g_hsh[(size_t)Mtot*Dc/8];  // hidden_states bf16
__device__ uint4  g_wqh[(size_t)Dc*Dc/8];    // weights bf16
__device__ uint4  g_wkh[(size_t)Dc*Dc/8];
__device__ uint4  g_wvh[(size_t)Dc*Dc/8];
__device__ uint4  g_woh[(size_t)Dc*Dc/8];
__device__ uint4  g_qh[(size_t)BHL*HDc/8];   // [bh][l][hd/2 u32] (q*0.125, rotated)
__device__ uint4  g_kh[(size_t)BHL*HDc/8];   // [bh][l][hd/2 u32]
__device__ uint4  g_vth[(size_t)BHL*HDc/8];  // [bh][d][Lc/2 u32] (V transposed)
__device__ uint4  g_ctxh[(size_t)Mtot*Dc/8]; // [B,L,D/2 u32]

// ---- helpers ----
__device__ __forceinline__ uint32_t pkbf2(float lo, float hi) {
    __nv_bfloat162 h = __float22bfloat162_rn(make_float2(lo, hi));
    return *(uint32_t*)&h;
}
__device__ __forceinline__ void mma_bf16(float* c, const uint32_t* a,
                                         uint32_t b0, uint32_t b1)
{
    asm volatile(
        "mma.sync.aligned.m16n8k16.row.col.f32.bf16.bf16.f32 "
        "{%0,%1,%2,%3}, {%4,%5,%6,%7}, {%8,%9}, {%0,%1,%2,%3};"
        : "+f"(c[0]), "+f"(c[1]), "+f"(c[2]), "+f"(c[3])
        : "r"(a[0]), "r"(a[1]), "r"(a[2]), "r"(a[3]), "r"(b0), "r"(b1));
}
__device__ __forceinline__ uint32_t smem_u32(const void* p) {
    return (uint32_t)__cvta_generic_to_shared(p);
}
__device__ __forceinline__ void ldsm_x4(uint32_t* r, uint32_t addr) {
    asm volatile("ldmatrix.sync.aligned.m8n8.x4.shared.b16 {%0,%1,%2,%3}, [%4];"
                 : "=r"(r[0]), "=r"(r[1]), "=r"(r[2]), "=r"(r[3]) : "r"(addr));
}
__device__ __forceinline__ void cpa16(uint32_t dst, const void* src) {
    asm volatile("cp.async.ca.shared.global [%0], [%1], 16;\n" :: "r"(dst), "l"(src));
}
// packed f32x2
__device__ __forceinline__ ull pk2(float lo, float hi) {
    ull r; asm("mov.b64 %0, {%1, %2};" : "=l"(r) : "f"(lo), "f"(hi)); return r;
}
__device__ __forceinline__ float2 upk2(ull v) {
    float2 r; asm("mov.b64 {%0, %1}, %2;" : "=f"(r.x), "=f"(r.y) : "l"(v)); return r;
}
__device__ __forceinline__ ull mulfma2(ull x, ull cx, ull y, ull cy) {
    ull t;
    asm("mul.rn.f32x2 %0, %1, %2;" : "=l"(t) : "l"(y), "l"(cy));
    asm("fma.rn.f32x2 %0, %1, %2, %0;" : "+l"(t) : "l"(x), "l"(cx));
    return t;
}
__device__ __forceinline__ float ex2f(float x) {
    float r; asm("ex2.approx.ftz.f32 %0, %1;" : "=f"(r) : "f"(x)); return r;
}
#define LOG2E 1.442695040888963f

// ============================================================
// fp32 -> packed bf16 conversion (hs + 4 weight matrices).
// ============================================================
__global__ __launch_bounds__(256)
void conv_kernel(const float* __restrict__ hs,
                 const float* __restrict__ Wq, const float* __restrict__ Wk,
                 const float* __restrict__ Wv, const float* __restrict__ Wo)
{
    const int y = blockIdx.y;
    const float* src; uint32_t* dst; int n4;
    if (y == 0)      { src = hs; dst = (uint32_t*)g_hsh; n4 = Mtot*Dc/4; }
    else if (y == 1) { src = Wq; dst = (uint32_t*)g_wqh; n4 = Dc*Dc/4; }
    else if (y == 2) { src = Wk; dst = (uint32_t*)g_wkh; n4 = Dc*Dc/4; }
    else if (y == 3) { src = Wv; dst = (uint32_t*)g_wvh; n4 = Dc*Dc/4; }
    else             { src = Wo; dst = (uint32_t*)g_woh; n4 = Dc*Dc/4; }
    const int idx = blockIdx.x * blockDim.x + threadIdx.x;
    if (idx >= n4) return;
    float4 v = ((const float4*)src)[idx];
    ((uint2*)dst)[idx] = make_uint2(pkbf2(v.x, v.y), pkbf2(v.z, v.w));
}

// ============================================================
// bf16 tile GEMM: pre-packed bf16 operands, cp.async double-buffer,
// ldmatrix fragments. (unchanged from round 14)
// ============================================================
template<int MODE>
__global__ __launch_bounds__(256)
void gemm_kernel(const float* __restrict__ bias0,
                 const float* __restrict__ bias1,
                 const float* __restrict__ bias2,
                 const float* __restrict__ residual)
{
    const uint32_t* Asrc; const uint32_t* Wsrc; const float* bias;
    const int z = (MODE == 0) ? blockIdx.z : 0;
    if (MODE == 0) {
        Asrc = (const uint32_t*)g_hsh;
        Wsrc = (z == 0) ? (const uint32_t*)g_wqh
             : (z == 1) ? (const uint32_t*)g_wkh : (const uint32_t*)g_wvh;
        bias = (z == 0) ? bias0 : (z == 1) ? bias1 : bias2;
    } else {
        Asrc = (const uint32_t*)g_ctxh;
        Wsrc = (const uint32_t*)g_woh;
        bias = bias0;
    }

    __shared__ uint32_t Au[2][128][20];
    __shared__ uint32_t Wu[2][128][20];

    const int tid  = threadIdx.x;
    const int lane = tid & 31;
    const int wid  = tid >> 5;
    const int g    = lane >> 2, tg = lane & 3;
    const int warpM = wid & 1, warpN = wid >> 1;
    const int m0 = blockIdx.y * 128;
    const int n0 = blockIdx.x * 128;

    const int a_lr = lane & 15;
    const int a_lc = (lane >> 4) << 2;
    const int b_lr = ((lane >> 4) << 3) + (lane & 7);
    const int b_lc = ((lane >> 3) & 1) << 2;

    const uint32_t* Abase = Asrc + (size_t)m0 * (Dc/2);
    const uint32_t* Wbase = Wsrc + (size_t)n0 * (Dc/2);

#define G_STAGE(k0_, buf_) do {                                                \
        _Pragma("unroll")                                                      \
        for (int i_ = 0; i_ < 2; i_++) {                                       \
            const int c_ = tid + i_ * 256;                                     \
            const int r_ = c_ >> 2, c4_ = (c_ & 3) * 4;                        \
            cpa16(smem_u32(&Au[buf_][r_][c4_]),                                \
                  Abase + (size_t)r_ * (Dc/2) + ((k0_) >> 1) + c4_);           \
            cpa16(smem_u32(&Wu[buf_][r_][c4_]),                                \
                  Wbase + (size_t)r_ * (Dc/2) + ((k0_) >> 1) + c4_);           \
        }                                                                      \
        asm volatile("cp.async.commit_group;\n" ::);                           \
    } while (0)

    float acc[4][4][4];
    #pragma unroll
    for (int mt = 0; mt < 4; mt++)
        #pragma unroll
        for (int nt = 0; nt < 4; nt++)
            #pragma unroll
            for (int i = 0; i < 4; i++) acc[mt][nt][i] = 0.f;

    G_STAGE(0, 0);
    asm volatile("cp.async.wait_group 0;\n" ::);
    __syncthreads();

    int cur = 0;
    for (int k0 = 0; k0 < Dc; k0 += 32) {
        const bool more = (k0 + 32 < Dc);
        if (more) G_STAGE(k0 + 32, cur ^ 1);

        #pragma unroll
        for (int ks = 0; ks < 2; ks++) {
            uint32_t af[4][4], bfr[2][4];
            #pragma unroll
            for (int mt = 0; mt < 4; mt++)
                ldsm_x4(af[mt], smem_u32(&Au[cur][warpM*64 + mt*16 + a_lr][ks*8 + a_lc]));
            #pragma unroll
            for (int ntp = 0; ntp < 2; ntp++)
                ldsm_x4(bfr[ntp], smem_u32(&Wu[cur][warpN*32 + ntp*16 + b_lr][ks*8 + b_lc]));
            #pragma unroll
            for (int mt = 0; mt < 4; mt++)
                #pragma unroll
                for (int nt = 0; nt < 4; nt++)
                    mma_bf16(acc[mt][nt], af[mt], bfr[nt>>1][(nt&1)*2], bfr[nt>>1][(nt&1)*2+1]);
        }

        if (more) asm volatile("cp.async.wait_group 0;\n" ::);
        __syncthreads();
        cur ^= 1;
    }
#undef G_STAGE

    // epilogue
    #pragma unroll
    for (int mt = 0; mt < 4; mt++) {
        const int mA = m0 + warpM * 64 + mt * 16 + g;
        #pragma unroll
        for (int nt = 0; nt < 4; nt++) {
            const int n = n0 + warpN * 32 + nt * 8 + 2 * tg;
            const float b0v = bias[n], b1v = bias[n + 1];
            #pragma unroll
            for (int rh = 0; rh < 2; rh++) {
                const int m = mA + rh * 8;
                float v0 = acc[mt][nt][rh * 2]     + b0v;
                float v1 = acc[mt][nt][rh * 2 + 1] + b1v;
                if (MODE == 0) {
                    const int bb = m >> 11;
                    const int l  = m & (Lc - 1);
                    const int h  = n >> 6;
                    const int d  = n & 63;
                    if (z == 2) {
                        __nv_bfloat16* vb = (__nv_bfloat16*)g_vth +
                            (((size_t)bb*Hc + h)*HDc + d)*Lc + l;
                        vb[0]  = __float2bfloat16_rn(v0);
                        vb[Lc] = __float2bfloat16_rn(v1);
                    } else {
                        float* out = (z == 0) ? g_q : g_k;
                        *(float2*)&out[(((size_t)bb*Hc + h)*Lc + l)*HDc + d] =
                            make_float2(v0, v1);
                    }
                } else {
                    const float2 rr = *(const float2*)&residual[(size_t)m*Dc + n];
                    *(float2*)&g_x[(size_t)m*Dc + n] = make_float2(v0 + rr.x, v1 + rr.y);
                }
            }
        }
    }
}

// ============================================================
// Rotary: fp32 in (g_q/g_k), packed-bf16 out + cos/sin table.
// ============================================================
__global__ __launch_bounds__(256)
void rotary_kernel(const float* __restrict__ phi)
{
    const int rest = blockIdx.x * blockDim.x + threadIdx.x;  // (b*H+h)*L + l
    if (rest >= BHL) return;
    const int l  = rest & (Lc - 1);
    const int bh = rest >> 11;
    const int h  = bh & (Hc - 1);
    const int b  = bh >> 4;

    const float p = phi[((size_t)b*Lc + l)*Hc + h];
    const float c = cosf(p);
    const float s = sinf(p);
    g_cs[rest] = make_float2(c, s);

    {
        const float4* qp = (const float4*)(g_q + (size_t)rest * HDc);
        float x[64];
        #pragma unroll
        for (int i = 0; i < 16; i++) *(float4*)&x[i*4] = qp[i];
        float r[64];
        #pragma unroll
        for (int d = 0; d < 32; d++) {
            r[d]      = (x[d] * c - x[d + 32] * s) * 0.125f;
            r[d + 32] = (x[d + 32] * c + x[d] * s) * 0.125f;
        }
        uint32_t* qd = (uint32_t*)g_qh + (size_t)rest * 32;
        #pragma unroll
        for (int i = 0; i < 32; i++) qd[i] = pkbf2(r[2*i], r[2*i + 1]);
    }
    {
        const float4* kp = (const float4*)(g_k + (size_t)rest * HDc);
        float x[64];
        #pragma unroll
        for (int i = 0; i < 16; i++) *(float4*)&x[i*4] = kp[i];
        float r[64];
        #pragma unroll
        for (int d = 0; d < 32; d++) {
            r[d]      = x[d] * c - x[d + 32] * s;
            r[d + 32] = x[d + 32] * c + x[d] * s;
        }
        uint32_t* kd = (uint32_t*)g_kh + (size_t)rest * 32;
        #pragma unroll
        for (int i = 0; i < 32; i++) kd[i] = pkbf2(r[2*i], r[2*i + 1]);
    }
}

// ============================================================
// bf16 tensor-core flash attention, v3:
//  - cp.async double-buffered K/V
//  - fixed-base softmax, P in registers (round 14)
//  - lsum via ones-column mma (B = const 1.0 bf16 fragment): removes
//    per-element lsum adds AND the final quad-shuffle reduce
//  - diagonal index check removed (dc(q,q)=c^2+s^2=1 > -0.7 always)
//  - packed f32x2 dc (SoA cos/sin), exp as single FFMA+EX2 with
//    amask pre-scaled by log2(e)
// grid (Lc/64, Hc, Bc), 128 thr = 4 warps, 16 q-rows per warp.
// ============================================================
#define ONES_BF2 0x3F803F80u

__global__ __launch_bounds__(128)
void attn_kernel(const float* __restrict__ amask)
{
    __shared__ uint32_t Qs[64][36];
    __shared__ uint32_t Ku[2][64][36];
    __shared__ uint32_t Vu[2][64][36];
    __shared__ float cskx[2][64], csky[2][64], am2[2][64];

    const int tid  = threadIdx.x;
    const int lane = tid & 31;
    const int warp = tid >> 5;
    const int g    = lane >> 2, tg = lane & 3;

    const int a_lr = lane & 15;
    const int a_lc = (lane >> 4) << 2;
    const int b_lr = ((lane >> 4) << 3) + (lane & 7);
    const int b_lc = ((lane >> 3) & 1) << 2;

    const int b  = blockIdx.z;
    const int h  = blockIdx.y;
    const int q0 = blockIdx.x * 64;
    const int bh = b * Hc + h;
    const size_t bhL = (size_t)bh * Lc;

    const uint32_t* qb = (const uint32_t*)g_qh  + bhL * 32;
    const uint32_t* kb = (const uint32_t*)g_kh  + bhL * 32;
    const uint32_t* vb = (const uint32_t*)g_vth + (size_t)bh * HDc * (Lc/2);

    const int row  = tid >> 1;
    const int half = tid & 1;

    // --- stage Q tile (already bf16) ---
    {
        const uint32_t* src = qb + (size_t)(q0 + row) * 32 + half * 16;
        *(uint4*)&Qs[row][half * 16]      = *(const uint4*)(src);
        *(uint4*)&Qs[row][half * 16 + 4]  = *(const uint4*)(src + 4);
        *(uint4*)&Qs[row][half * 16 + 8]  = *(const uint4*)(src + 8);
        *(uint4*)&Qs[row][half * 16 + 12] = *(const uint4*)(src + 12);
    }
    __syncwarp();

    uint32_t qa[4][4];
    #pragma unroll
    for (int ks = 0; ks < 4; ks++)
        ldsm_x4(qa[ks], smem_u32(&Qs[warp*16 + a_lr][ks*8 + a_lc]));

    const int qrow = warp * 16 + g;
    const float2 csq0 = g_cs[bhL + q0 + qrow];
    const float2 csq1 = g_cs[bhL + q0 + qrow + 8];
    const ull cq0x = pk2(csq0.x, csq0.x), cq0y = pk2(csq0.y, csq0.y);
    const ull cq1x = pk2(csq1.x, csq1.x), cq1y = pk2(csq1.y, csq1.y);
    const int qg0 = q0 + qrow, qg1 = q0 + qrow + 8;

#define STAGE_KV(kt_, buf_) do {                                              \
        _Pragma("unroll")                                                     \
        for (int i_ = 0; i_ < 4; i_++) {                                      \
            const int c_ = tid + i_ * 128;                                    \
            const int r_ = c_ >> 3, c4_ = (c_ & 7) * 4;                       \
            cpa16(smem_u32(&Ku[buf_][r_][c4_]),                               \
                  kb + (size_t)((kt_) + r_) * 32 + c4_);                      \
            cpa16(smem_u32(&Vu[buf_][r_][c4_]),                               \
                  vb + (size_t)r_ * (Lc/2) + ((kt_) >> 1) + c4_);             \
        }                                                                     \
        asm volatile("cp.async.commit_group;\n" ::);                          \
    } while (0)
#define STAGE_CSAM(kt_, buf_) do {                                            \
        if (tid < 64) {                                                       \
            float2 cs_ = g_cs[bhL + (kt_) + tid];                             \
            cskx[buf_][tid] = cs_.x;                                          \
            csky[buf_][tid] = cs_.y;                                          \
            am2[buf_][tid]  = amask[(size_t)b * Lc + (kt_) + tid] * LOG2E;    \
        }                                                                     \
    } while (0)

    STAGE_KV(0, 0);
    STAGE_CSAM(0, 0);
    asm volatile("cp.async.wait_group 0;\n" ::);
    __syncthreads();

    float lacc[4] = {0.f, 0.f, 0.f, 0.f};   // ones-column row-sum accumulator
    float oacc[8][4];
    #pragma unroll
    for (int nt = 0; nt < 8; nt++)
        #pragma unroll
        for (int i = 0; i < 4; i++) oacc[nt][i] = 0.f;

    int cur = 0;
    for (int kt = 0; kt < Lc; kt += 64) {
        const bool more = (kt + 64 < Lc);
        if (more) {
            STAGE_KV(kt + 64, cur ^ 1);
            STAGE_CSAM(kt + 64, cur ^ 1);
        }

        // --- scores: S[16 x 64] per warp ---
        float sacc[8][4];
        #pragma unroll
        for (int nt = 0; nt < 8; nt++)
            #pragma unroll
            for (int i = 0; i < 4; i++) sacc[nt][i] = 0.f;
        #pragma unroll
        for (int ks = 0; ks < 4; ks++) {
            #pragma unroll
            for (int ntp = 0; ntp < 4; ntp++) {
                uint32_t kb4[4];
                ldsm_x4(kb4, smem_u32(&Ku[cur][ntp*16 + b_lr][ks*8 + b_lc]));
                mma_bf16(sacc[2*ntp],     qa[ks], kb4[0], kb4[1]);
                mma_bf16(sacc[2*ntp + 1], qa[ks], kb4[2], kb4[3]);
            }
        }

        // --- mask + fixed-base exp (fp32, packed dc, P in registers) ---
        #pragma unroll
        for (int nt = 0; nt < 8; nt++) {
            const int c0 = nt * 8 + 2 * tg;
            const ull X = *(const ull*)&cskx[cur][c0];   // (ck0x, ck1x)
            const ull Y = *(const ull*)&csky[cur][c0];   // (ck0y, ck1y)
            const float2 d0 = upk2(mulfma2(X, cq0x, Y, cq0y));  // dc for q row g
            const float2 d1 = upk2(mulfma2(X, cq1x, Y, cq1y));  // dc for q row g+8
            const float2 aa = *(const float2*)&am2[cur][c0];

            const float p0 = (d0.x < -0.7f) ? 0.f : ex2f(fmaf(sacc[nt][0], LOG2E, aa.x));
            const float p1 = (d0.y < -0.7f) ? 0.f : ex2f(fmaf(sacc[nt][1], LOG2E, aa.y));
            const float p2 = (d1.x < -0.7f) ? 0.f : ex2f(fmaf(sacc[nt][2], LOG2E, aa.x));
            const float p3 = (d1.y < -0.7f) ? 0.f : ex2f(fmaf(sacc[nt][3], LOG2E, aa.y));
            sacc[nt][0] = p0; sacc[nt][1] = p1;
            sacc[nt][2] = p2; sacc[nt][3] = p3;
        }

        // --- PV: O += P @ V ; lsum += P @ 1 (ones-column mma) ---
        #pragma unroll
        for (int ks = 0; ks < 4; ks++) {
            uint32_t pa[4];
            pa[0] = pkbf2(sacc[2*ks    ][0], sacc[2*ks    ][1]);
            pa[1] = pkbf2(sacc[2*ks    ][2], sacc[2*ks    ][3]);
            pa[2] = pkbf2(sacc[2*ks + 1][0], sacc[2*ks + 1][1]);
            pa[3] = pkbf2(sacc[2*ks + 1][2], sacc[2*ks + 1][3]);
            #pragma unroll
            for (int ntp = 0; ntp < 4; ntp++) {
                uint32_t vb4[4];
                ldsm_x4(vb4, smem_u32(&Vu[cur][ntp*16 + b_lr][ks*8 + b_lc]));
                mma_bf16(oacc[2*ntp],     pa, vb4[0], vb4[1]);
                mma_bf16(oacc[2*ntp + 1], pa, vb4[2], vb4[3]);
            }
            mma_bf16(lacc, pa, ONES_BF2, ONES_BF2);
        }

        if (more) asm volatile("cp.async.wait_group 0;\n" ::);
        __syncthreads();
        cur ^= 1;
    }

    // --- finalize: lacc already holds full row sums ---
    const float inv0 = 1.f / lacc[0];   // row g
    const float inv1 = 1.f / lacc[2];   // row g+8

    uint32_t* ctxu = (uint32_t*)g_ctxh;
    const size_t base0 = ((size_t)(b * Lc + qg0) * Dc + h * HDc) >> 1;
    const size_t base1 = ((size_t)(b * Lc + qg1) * Dc + h * HDc) >> 1;
    #pragma unroll
    for (int nt = 0; nt < 8; nt++) {
        const int d = nt * 8 + 2 * tg;
        ctxu[base0 + (d >> 1)] = pkbf2(oacc[nt][0] * inv0, oacc[nt][1] * inv0);
        ctxu[base1 + (d >> 1)] = pkbf2(oacc[nt][2] * inv1, oacc[nt][3] * inv1);
    }
#undef STAGE_KV
#undef STAGE_CSAM
}

// ============================================================
// LayerNorm over last dim (1024). one block per row, 256 threads.
// ============================================================
__global__ __launch_bounds__(256)
void ln_kernel(const float* __restrict__ gamma, const float* __restrict__ beta,
               float* __restrict__ out)
{
    const int row = blockIdx.x;
    const int tid = threadIdx.x;
    const float4 v = ((const float4*)(g_x + (size_t)row * Dc))[tid];
    float s  = v.x + v.y + v.z + v.w;
    float sq = v.x*v.x + v.y*v.y + v.z*v.z + v.w*v.w;
    #pragma unroll
    for (int off = 16; off > 0; off >>= 1) {
        s  += __shfl_xor_sync(0xffffffffu, s,  off);
        sq += __shfl_xor_sync(0xffffffffu, sq, off);
    }
    __shared__ float ssum[8], ssq[8];
    const int w = tid >> 5;
    if ((tid & 31) == 0) { ssum[w] = s; ssq[w] = sq; }
    __syncthreads();
    if (tid == 0) {
        float ts = 0.f, tq = 0.f;
        #pragma unroll
        for (int i = 0; i < 8; i++) { ts += ssum[i]; tq += ssq[i]; }
        ssum[0] = ts; ssq[0] = tq;
    }
    __syncthreads();
    const float mean = ssum[0] * (1.f / Dc);
    const float var  = ssq[0]  * (1.f / Dc) - mean * mean;
    const float inv  = rsqrtf(var + 1e-12f);
    const float4 gv = ((const float4*)gamma)[tid];
    const float4 bv = ((const float4*)beta)[tid];
    float4 ov;
    ov.x = (v.x - mean) * inv * gv.x + bv.x;
    ov.y = (v.y - mean) * inv * gv.y + bv.y;
    ov.z = (v.z - mean) * inv * gv.z + bv.z;
    ov.w = (v.w - mean) * inv * gv.w + bv.w;
    ((float4*)out)[(size_t)row * (Dc/4) + tid] = ov;
}

// ============================================================
// launch
// ============================================================
extern "C" void kernel_launch(void* const* d_in, const int* in_sizes, int n_in,
                              void* d_out, int out_size)
{
    const float* hs    = (const float*)d_in[0];
    const float* amask = (const float*)d_in[1];
    const float* phi   = (const float*)d_in[2];
    const float* Wq    = (const float*)d_in[3];
    const float* bq    = (const float*)d_in[4];
    const float* Wk    = (const float*)d_in[5];
    const float* bk    = (const float*)d_in[6];
    const float* Wv    = (const float*)d_in[7];
    const float* bv    = (const float*)d_in[8];
    const float* Wo    = (const float*)d_in[9];
    const float* bo    = (const float*)d_in[10];
    const float* lng   = (const float*)d_in[11];
    const float* lnb   = (const float*)d_in[12];
    float* out = (float*)d_out;

    // 0) pack hs + weights to bf16
    dim3 gc((Mtot*Dc/4 + 255)/256, 5);
    conv_kernel<<<gc, 256>>>(hs, Wq, Wk, Wv, Wo);

    // 1) QKV projections -> g_q/g_k fp32, g_vth bf16 (transposed)
    dim3 g0(Dc/128, Mtot/128, 3);
    gemm_kernel<0><<<g0, 256>>>(bq, bk, bv, nullptr);

    // 2) rotary -> g_qh/g_kh packed bf16 + cos/sin table
    rotary_kernel<<<BHL/256, 256>>>(phi);

    // 3) attention -> g_ctxh packed bf16
    dim3 g2(Lc/64, Hc, Bc);
    attn_kernel<<<g2, 128>>>(amask);

    // 4) output projection + residual -> g_x
    dim3 g3(Dc/128, Mtot/128, 1);
    gemm_kernel<1><<<g3, 256>>>(bo, nullptr, nullptr, hs);

    // 5) layernorm -> d_out
    ln_kernel<<<Mtot, 256>>>(lng, lnb, out);
}